// round 5
// baseline (speedup 1.0000x reference)
#include <cuda_runtime.h>
#include <cuda_bf16.h>
#include <math.h>
#include <stdint.h>

#define Nn 50000
#define Ee 800000
#define Gg 50
#define Lr 3
#define TILES 391            // ceil(50000/128)
#define PADK 136             // smem row stride in bf16 (272B, conflict-free for ldmatrix)

// ---------------- static device scratch (no runtime alloc allowed) ----------------
__device__ float g_qkvs[(size_t)Nn * 512];   // per layer: [q | k | v | x_r] each 128
__device__ float g_outb[(size_t)Nn * 128];   // attention output / gated output
__device__ float g_xcur[(size_t)Nn * 128];   // current node features (post layer)
__device__ float g_alpha[(size_t)Ee * 4];    // per-edge per-head logits -> exp weights
__device__ int   g_amax[(size_t)Nn * 4];     // ordered-int encoded segment max
__device__ float g_den[(size_t)Nn * 4];      // softmax denominators
__device__ float g_bnsum[128];
__device__ float g_bnsq[128];
__device__ float g_bnsc[128];
__device__ float g_bnsh[128];
__device__ int   g_esrc[Ee];
__device__ int   g_edst[Ee];
__device__ int   g_batch[Nn];
__device__ float g_gsum[Gg * 128];
__device__ float g_gcnt[Gg];
__device__ int   g_flags[2];
// W split+transpose staging: [l*4+mat][n][k] bf16 hi/lo, unswizzled
__device__ __nv_bfloat16 g_Whi[12 * 16384];
__device__ __nv_bfloat16 g_Wlo[12 * 16384];

// ---------------- helpers ----------------
__device__ __forceinline__ int fenc(float f) {
    int i = __float_as_int(f);
    return i >= 0 ? i : i ^ 0x7fffffff;
}
__device__ __forceinline__ float fdec(int i) {
    return __int_as_float(i >= 0 ? i : i ^ 0x7fffffff);
}
#define ENC_NEG_INF 0x807fffff

__device__ __forceinline__ uint32_t smem_u32(const void* p) {
    uint32_t a;
    asm("{ .reg .u64 t; cvta.to.shared.u64 t, %1; cvt.u32.u64 %0, t; }" : "=r"(a) : "l"(p));
    return a;
}

// ---------------- dtype sniffing: int64 vs int32 index tensors ----------------
__global__ void k_detect(const void* ei, const void* ba) {
    if (threadIdx.x == 0 && blockIdx.x == 0) {
        const unsigned int* p = (const unsigned int*)ei;
        unsigned int acc = 0;
        long long half_e = (long long)Ee - 1;
        for (int j = 0; j < 64; j++) {
            long long i = half_e * j / 63;
            acc |= p[2 * i + 1];
        }
        g_flags[0] = (acc == 0) ? 1 : 0;
        const unsigned int* q = (const unsigned int*)ba;
        unsigned int acc2 = 0;
        long long half_n = (long long)Nn / 2 - 1;
        for (int j = 0; j < 64; j++) {
            long long i = half_n * j / 63;
            acc2 |= q[2 * i + 1];
        }
        g_flags[1] = (acc2 == 0) ? 1 : 0;
    }
}

__global__ void k_convert(const void* ei, const void* ba) {
    int i = blockIdx.x * blockDim.x + threadIdx.x;
    int f0 = g_flags[0], f1 = g_flags[1];
    if (i < 2 * Ee) {
        int v = f0 ? (int)((const long long*)ei)[i] : ((const int*)ei)[i];
        if (i < Ee) g_esrc[i] = v;
        else        g_edst[i - Ee] = v;
    }
    if (i < Nn) {
        g_batch[i] = f1 ? (int)((const long long*)ba)[i] : ((const int*)ba)[i];
    }
}

// ---------------- per-layer init ----------------
__global__ void k_init() {
    int i = blockIdx.x * blockDim.x + threadIdx.x;
    if (i < Nn * 128) g_outb[i] = 0.0f;
    if (i < Nn * 4) { g_den[i] = 0.0f; g_amax[i] = ENC_NEG_INF; }
    if (i < 128) { g_bnsum[i] = 0.0f; g_bnsq[i] = 0.0f; }
}

// ---------------- W split + transpose (12 mats, once per launch) --------------
// staging[j][k] = W[k][j]  (mma B operand wants [N,K] row-major)
__global__ void k_splitW(const float* __restrict__ Wq, const float* __restrict__ Wk,
                         const float* __restrict__ Wv, const float* __restrict__ Ws) {
    int i = blockIdx.x * blockDim.x + threadIdx.x;   // over 12*2048 chunks of 8
    if (i >= 12 * 2048) return;
    int lm = i >> 11;
    int cidx = i & 2047;
    int j = cidx >> 4;          // output col / B row
    int kc = cidx & 15;         // k chunk of 8
    int l = lm >> 2, mat = lm & 3;
    const float* W = (mat == 0 ? Wq : mat == 1 ? Wk : mat == 2 ? Wv : Ws)
                   + (size_t)l * 16384;
    __nv_bfloat16 hi[8], lo[8];
    #pragma unroll
    for (int s = 0; s < 8; s++) {
        float v = W[(kc * 8 + s) * 128 + j];
        hi[s] = __float2bfloat16(v);
        lo[s] = __float2bfloat16(v - __bfloat162float(hi[s]));
    }
    size_t base = (size_t)lm * 16384 + j * 128 + kc * 8;
    *(uint4*)(g_Whi + base) = *(uint4*)hi;
    *(uint4*)(g_Wlo + base) = *(uint4*)lo;
}

// ---------------- warp-MMA GEMM: 128x128x128 tile, bf16x3 emulated fp32 --------
// grid (TILES, 4 mats), 256 threads. dyn smem: Ahi|Alo|Whi|Wlo, 128x136 bf16 each.
#define SM_AHI 0
#define SM_ALO (128 * PADK * 2)
#define SM_WHI (2 * 128 * PADK * 2)
#define SM_WLO (3 * 128 * PADK * 2)
#define SM_TOT (4 * 128 * PADK * 2)

__global__ void __launch_bounds__(256) k_gemm_mma(
    const float* __restrict__ Asrc,  // nullptr -> g_xcur
    int l, const float* __restrict__ bq, const float* __restrict__ bk,
    const float* __restrict__ bv, const float* __restrict__ bs)
{
    extern __shared__ __align__(16) char sm[];
    int tid = threadIdx.x;
    int t = blockIdx.x, mat = blockIdx.y;
    const float* Ap = Asrc ? Asrc : g_xcur;

    // ---- load & split A: thread handles (row, 64-col half) ----
    {
        int r = tid >> 1, hf = tid & 1;
        int row = t * 128 + r;
        __nv_bfloat16* dhi = (__nv_bfloat16*)(sm + SM_AHI) + r * PADK + hf * 64;
        __nv_bfloat16* dlo = (__nv_bfloat16*)(sm + SM_ALO) + r * PADK + hf * 64;
        if (row < Nn) {
            const float4* src = (const float4*)(Ap + (size_t)row * 128 + hf * 64);
            #pragma unroll
            for (int c = 0; c < 8; c++) {   // 8 chunks of 8 floats
                float4 v0 = src[c * 2], v1 = src[c * 2 + 1];
                float vs[8] = {v0.x, v0.y, v0.z, v0.w, v1.x, v1.y, v1.z, v1.w};
                __nv_bfloat16 hi[8], lo[8];
                #pragma unroll
                for (int s = 0; s < 8; s++) {
                    hi[s] = __float2bfloat16(vs[s]);
                    lo[s] = __float2bfloat16(vs[s] - __bfloat162float(hi[s]));
                }
                *(uint4*)(dhi + c * 8) = *(uint4*)hi;
                *(uint4*)(dlo + c * 8) = *(uint4*)lo;
            }
        } else {
            uint4 z = make_uint4(0, 0, 0, 0);
            #pragma unroll
            for (int c = 0; c < 8; c++) {
                *(uint4*)(dhi + c * 8) = z;
                *(uint4*)(dlo + c * 8) = z;
            }
        }
    }
    // ---- load W hi/lo from staging ----
    {
        int n = tid >> 1, hf = tid & 1;
        size_t base = (size_t)(l * 4 + mat) * 16384 + n * 128 + hf * 64;
        const uint4* shi = (const uint4*)(g_Whi + base);
        const uint4* slo = (const uint4*)(g_Wlo + base);
        uint4* dhi = (uint4*)((__nv_bfloat16*)(sm + SM_WHI) + n * PADK + hf * 64);
        uint4* dlo = (uint4*)((__nv_bfloat16*)(sm + SM_WLO) + n * PADK + hf * 64);
        #pragma unroll
        for (int c = 0; c < 8; c++) { dhi[c] = shi[c]; dlo[c] = slo[c]; }
    }
    __syncthreads();

    int wid = tid >> 5, lane = tid & 31;
    int wr = wid >> 1, wc = wid & 1;       // warp tile: rows wr*32, cols wc*64
    int m0 = wr * 32, n0 = wc * 64;

    // ldmatrix lane addressing
    int quad = lane >> 3, qr = lane & 7;
    int a_row = ((quad & 1) << 3) + qr;    // 0..15
    int a_kof = (quad & 2) << 2;           // 0 or 8
    int b_row = qr;
    int b_kof = (quad & 1) << 3;           // x2 uses lanes 0..15

    uint32_t sb = smem_u32(sm);
    uint32_t aBase[2];                     // per pass A source (hi, hi, lo)
    aBase[0] = sb + SM_AHI;
    aBase[1] = sb + SM_ALO;
    uint32_t wBase[2];
    wBase[0] = sb + SM_WHI;
    wBase[1] = sb + SM_WLO;

    float acc[2][8][4];
    #pragma unroll
    for (int mt = 0; mt < 2; mt++)
        #pragma unroll
        for (int nt = 0; nt < 8; nt++)
            #pragma unroll
            for (int c = 0; c < 4; c++) acc[mt][nt][c] = 0.0f;

    #pragma unroll
    for (int pass = 0; pass < 3; pass++) {
        uint32_t ab = aBase[pass == 2 ? 1 : 0];
        uint32_t wb = wBase[pass == 1 ? 1 : 0];
        #pragma unroll
        for (int ks = 0; ks < 8; ks++) {
            int k0 = ks * 16;
            uint32_t af[2][4];
            #pragma unroll
            for (int mt = 0; mt < 2; mt++) {
                uint32_t addr = ab + ((m0 + mt * 16 + a_row) * PADK + k0 + a_kof) * 2;
                asm volatile("ldmatrix.sync.aligned.m8n8.x4.shared.b16 {%0,%1,%2,%3}, [%4];"
                             : "=r"(af[mt][0]), "=r"(af[mt][1]), "=r"(af[mt][2]), "=r"(af[mt][3])
                             : "r"(addr));
            }
            #pragma unroll
            for (int nt = 0; nt < 8; nt++) {
                uint32_t bf[2];
                uint32_t addr = wb + ((n0 + nt * 8 + b_row) * PADK + k0 + b_kof) * 2;
                asm volatile("ldmatrix.sync.aligned.m8n8.x2.shared.b16 {%0,%1}, [%2];"
                             : "=r"(bf[0]), "=r"(bf[1]) : "r"(addr));
                #pragma unroll
                for (int mt = 0; mt < 2; mt++) {
                    asm volatile(
                        "mma.sync.aligned.m16n8k16.row.col.f32.bf16.bf16.f32 "
                        "{%0,%1,%2,%3}, {%4,%5,%6,%7}, {%8,%9}, {%0,%1,%2,%3};"
                        : "+f"(acc[mt][nt][0]), "+f"(acc[mt][nt][1]),
                          "+f"(acc[mt][nt][2]), "+f"(acc[mt][nt][3])
                        : "r"(af[mt][0]), "r"(af[mt][1]), "r"(af[mt][2]), "r"(af[mt][3]),
                          "r"(bf[0]), "r"(bf[1]));
                }
            }
        }
    }

    // ---- epilogue: D fragment rows lane/4 (+8), cols (lane%3? no, (lane&3)*2) ----
    const float* bias = (mat == 0 ? bq : mat == 1 ? bk : mat == 2 ? bv : bs) + l * 128;
    int drow = lane >> 2, dcol = (lane & 3) * 2;
    #pragma unroll
    for (int mt = 0; mt < 2; mt++) {
        #pragma unroll
        for (int nt = 0; nt < 8; nt++) {
            int col = n0 + nt * 8 + dcol;
            float b0 = bias[col], b1 = bias[col + 1];
            int r0 = t * 128 + m0 + mt * 16 + drow;
            if (r0 < Nn) {
                float2 v = {acc[mt][nt][0] + b0, acc[mt][nt][1] + b1};
                *(float2*)(g_qkvs + (size_t)r0 * 512 + mat * 128 + col) = v;
            }
            int r1 = r0 + 8;
            if (r1 < Nn) {
                float2 v = {acc[mt][nt][2] + b0, acc[mt][nt][3] + b1};
                *(float2*)(g_qkvs + (size_t)r1 * 512 + mat * 128 + col) = v;
            }
        }
    }
}

// ---------------- attention logits + segment max (warp per edge) ----------------
__global__ void k_alpha(const float* __restrict__ edge_attr,
                        const float* __restrict__ We, const float* __restrict__ be)
{
    int wid = (blockIdx.x * blockDim.x + threadIdx.x) >> 5;
    int lane = threadIdx.x & 31;
    if (wid >= Ee) return;
    int src = g_esrc[wid], dst = g_edst[wid];
    float4 qv = ((const float4*)(g_qkvs + (size_t)dst * 512))[lane];
    float4 kv = ((const float4*)(g_qkvs + (size_t)src * 512 + 128))[lane];
    float a0 = edge_attr[wid * 2 + 0];
    float a1 = edge_attr[wid * 2 + 1];
    float4 w0 = ((const float4*)We)[lane];
    float4 w1 = ((const float4*)(We + 128))[lane];
    float4 bb = ((const float4*)be)[lane];
    float4 ee;
    ee.x = fmaf(a0, w0.x, fmaf(a1, w1.x, bb.x));
    ee.y = fmaf(a0, w0.y, fmaf(a1, w1.y, bb.y));
    ee.z = fmaf(a0, w0.z, fmaf(a1, w1.z, bb.z));
    ee.w = fmaf(a0, w0.w, fmaf(a1, w1.w, bb.w));
    float d = qv.x * (kv.x + ee.x) + qv.y * (kv.y + ee.y)
            + qv.z * (kv.z + ee.z) + qv.w * (kv.w + ee.w);
    d += __shfl_xor_sync(0xffffffffu, d, 4);
    d += __shfl_xor_sync(0xffffffffu, d, 2);
    d += __shfl_xor_sync(0xffffffffu, d, 1);
    if ((lane & 7) == 0) {
        int h = lane >> 3;
        float al = d * 0.17677669529663687f;  // 1/sqrt(32)
        g_alpha[(size_t)wid * 4 + h] = al;
        atomicMax(&g_amax[dst * 4 + h], fenc(al));
    }
}

// ---------------- exp + denominator (thread per edge-head) ----------------
__global__ void k_exp() {
    int i = blockIdx.x * blockDim.x + threadIdx.x;
    if (i >= Ee * 4) return;
    int e = i >> 2, h = i & 3;
    int dst = g_edst[e];
    float al = g_alpha[i];
    float m = fdec(g_amax[dst * 4 + h]);
    float ex = expf(al - m);
    g_alpha[i] = ex;
    atomicAdd(&g_den[dst * 4 + h], ex);
}

// ---------------- weighted message scatter (warp per edge) ----------------
__global__ void k_msg(const float* __restrict__ edge_attr,
                      const float* __restrict__ We, const float* __restrict__ be)
{
    int wid = (blockIdx.x * blockDim.x + threadIdx.x) >> 5;
    int lane = threadIdx.x & 31;
    if (wid >= Ee) return;
    int src = g_esrc[wid], dst = g_edst[wid];
    int h = lane >> 3;
    float ex = g_alpha[(size_t)wid * 4 + h];
    float den = g_den[dst * 4 + h];
    float w = ex / (den + 1e-16f);
    float4 vv = ((const float4*)(g_qkvs + (size_t)src * 512 + 256))[lane];
    float a0 = edge_attr[wid * 2 + 0];
    float a1 = edge_attr[wid * 2 + 1];
    float4 w0 = ((const float4*)We)[lane];
    float4 w1 = ((const float4*)(We + 128))[lane];
    float4 bb = ((const float4*)be)[lane];
    float mx = (vv.x + fmaf(a0, w0.x, fmaf(a1, w1.x, bb.x))) * w;
    float my = (vv.y + fmaf(a0, w0.y, fmaf(a1, w1.y, bb.y))) * w;
    float mz = (vv.z + fmaf(a0, w0.z, fmaf(a1, w1.z, bb.z))) * w;
    float mw = (vv.w + fmaf(a0, w0.w, fmaf(a1, w1.w, bb.w))) * w;
    float* o = g_outb + (size_t)dst * 128 + lane * 4;
    asm volatile("red.global.add.v4.f32 [%0], {%1,%2,%3,%4};"
                 :: "l"(o), "f"(mx), "f"(my), "f"(mz), "f"(mw) : "memory");
}

// ---------------- beta gate + BN partial stats (warp per node, 8 nodes/block) ----
__global__ void k_gate(const float* __restrict__ Wbeta) {
    __shared__ float ssum[128];
    __shared__ float ssq[128];
    int tid = threadIdx.x;
    if (tid < 128) { ssum[tid] = 0.0f; ssq[tid] = 0.0f; }
    __syncthreads();
    int lane = tid & 31;
    int n = blockIdx.x * 8 + (tid >> 5);
    if (n < Nn) {
        float4 o = ((const float4*)(g_outb + (size_t)n * 128))[lane];
        float4 xr = ((const float4*)(g_qkvs + (size_t)n * 512 + 384))[lane];
        float4 w1 = ((const float4*)Wbeta)[lane];
        float4 w2 = ((const float4*)(Wbeta + 128))[lane];
        float4 w3 = ((const float4*)(Wbeta + 256))[lane];
        float s = o.x * w1.x + o.y * w1.y + o.z * w1.z + o.w * w1.w
                + xr.x * w2.x + xr.y * w2.y + xr.z * w2.z + xr.w * w2.w
                + (o.x - xr.x) * w3.x + (o.y - xr.y) * w3.y
                + (o.z - xr.z) * w3.z + (o.w - xr.w) * w3.w;
        #pragma unroll
        for (int m = 16; m > 0; m >>= 1) s += __shfl_xor_sync(0xffffffffu, s, m);
        float g = 1.0f / (1.0f + expf(-s));
        float4 no;
        no.x = g * xr.x + (1.0f - g) * o.x;
        no.y = g * xr.y + (1.0f - g) * o.y;
        no.z = g * xr.z + (1.0f - g) * o.z;
        no.w = g * xr.w + (1.0f - g) * o.w;
        ((float4*)(g_outb + (size_t)n * 128))[lane] = no;
        int c = lane * 4;
        atomicAdd(&ssum[c + 0], no.x); atomicAdd(&ssq[c + 0], no.x * no.x);
        atomicAdd(&ssum[c + 1], no.y); atomicAdd(&ssq[c + 1], no.y * no.y);
        atomicAdd(&ssum[c + 2], no.z); atomicAdd(&ssq[c + 2], no.z * no.z);
        atomicAdd(&ssum[c + 3], no.w); atomicAdd(&ssq[c + 3], no.w * no.w);
    }
    __syncthreads();
    if (tid < 128) {
        atomicAdd(&g_bnsum[tid], ssum[tid]);
        atomicAdd(&g_bnsq[tid], ssq[tid]);
    }
}

// ---------------- BN finalize ----------------
__global__ void k_bnstats(const float* __restrict__ gamma, const float* __restrict__ beta) {
    int c = threadIdx.x;
    if (c < 128) {
        float mu = g_bnsum[c] / (float)Nn;
        float var = g_bnsq[c] / (float)Nn - mu * mu;
        float rs = rsqrtf(var + 1e-5f);
        float sc = gamma[c] * rs;
        g_bnsc[c] = sc;
        g_bnsh[c] = beta[c] - mu * sc;
    }
}

// ---------------- BN apply + ELU ----------------
__global__ void k_bnelu() {
    int i = blockIdx.x * blockDim.x + threadIdx.x;
    if (i >= Nn * 128) return;
    int c = i & 127;
    float y = g_outb[i] * g_bnsc[c] + g_bnsh[c];
    g_xcur[i] = y > 0.0f ? y : expm1f(y);
}

// ---------------- readout ----------------
__global__ void k_poolinit() {
    int i = blockIdx.x * blockDim.x + threadIdx.x;
    if (i < Gg * 128) g_gsum[i] = 0.0f;
    if (i < Gg) g_gcnt[i] = 0.0f;
}

__global__ void k_pool() {
    int wid = (blockIdx.x * blockDim.x + threadIdx.x) >> 5;
    int lane = threadIdx.x & 31;
    if (wid >= Nn) return;
    int b = g_batch[wid];
    float4 v = ((const float4*)(g_xcur + (size_t)wid * 128))[lane];
    float* o = g_gsum + b * 128 + lane * 4;
    atomicAdd(o + 0, v.x);
    atomicAdd(o + 1, v.y);
    atomicAdd(o + 2, v.z);
    atomicAdd(o + 3, v.w);
    if (lane == 0) atomicAdd(&g_gcnt[b], 1.0f);
}

__global__ void k_read(const float* __restrict__ Wout, const float* __restrict__ bout,
                       const float* __restrict__ obias, float* __restrict__ out) {
    __shared__ float red[128];
    int g = blockIdx.x;
    int c = threadIdx.x;
    float cnt = g_gcnt[g];
    float d = fmaxf(cnt, 1.0f);
    red[c] = g_gsum[g * 128 + c] / d * Wout[c];
    __syncthreads();
    for (int s = 64; s > 0; s >>= 1) {
        if (c < s) red[c] += red[c + s];
        __syncthreads();
    }
    if (c == 0) out[g] = red[0] + bout[0] + obias[0];
}

// ---------------- host ----------------
extern "C" void kernel_launch(void* const* d_in, const int* in_sizes, int n_in,
                              void* d_out, int out_size) {
    const float* x    = (const float*)d_in[0];
    const void*  ei   = d_in[1];
    const float* ea   = (const float*)d_in[2];
    const void*  ba   = d_in[3];
    const float* Wq   = (const float*)d_in[4];
    const float* bq   = (const float*)d_in[5];
    const float* Wk   = (const float*)d_in[6];
    const float* bk   = (const float*)d_in[7];
    const float* Wv   = (const float*)d_in[8];
    const float* bv   = (const float*)d_in[9];
    const float* We   = (const float*)d_in[10];
    const float* be   = (const float*)d_in[11];
    const float* Ws   = (const float*)d_in[12];
    const float* bs   = (const float*)d_in[13];
    const float* Wb   = (const float*)d_in[14];
    const float* gam  = (const float*)d_in[15];
    const float* bet  = (const float*)d_in[16];
    const float* Wout = (const float*)d_in[17];
    const float* bout = (const float*)d_in[18];
    const float* obia = (const float*)d_in[19];

    static int smem_set = 0;
    if (!smem_set) {
        cudaFuncSetAttribute(k_gemm_mma, cudaFuncAttributeMaxDynamicSharedMemorySize, SM_TOT);
        smem_set = 1;
    }

    k_detect<<<1, 32>>>(ei, ba);
    k_convert<<<(2 * Ee + 255) / 256, 256>>>(ei, ba);
    k_splitW<<<(12 * 2048 + 255) / 256, 256>>>(Wq, Wk, Wv, Ws);

    for (int l = 0; l < Lr; l++) {
        k_init<<<(Nn * 128 + 255) / 256, 256>>>();
        k_gemm_mma<<<dim3(TILES, 4), 256, SM_TOT>>>(
            l == 0 ? x : nullptr, l, bq, bk, bv, bs);
        k_alpha<<<(Ee * 32) / 256, 256>>>(ea, We + l * 256, be + l * 128);
        k_exp<<<(Ee * 4 + 255) / 256, 256>>>();
        k_msg<<<(Ee * 32) / 256, 256>>>(ea, We + l * 256, be + l * 128);
        k_gate<<<(Nn + 7) / 8, 256>>>(Wb + l * 384);
        k_bnstats<<<1, 128>>>(gam + l * 128, bet + l * 128);
        k_bnelu<<<(Nn * 128 + 255) / 256, 256>>>();
    }

    k_poolinit<<<(Gg * 128 + 255) / 256, 256>>>();
    k_pool<<<(Nn * 32 + 255) / 256, 256>>>();
    k_read<<<Gg, 128>>>(Wout, bout, obia, (float*)d_out);
}

// round 7
// speedup vs baseline: 1.7093x; 1.7093x over previous
#include <cuda_runtime.h>
#include <cuda_bf16.h>
#include <math.h>
#include <stdint.h>

#define Nn 50000
#define Ee 800000
#define Gg 50
#define Lr 3
#define TILES 391            // ceil(50000/128)
#define PADK 136             // smem row stride in bf16 (272B, conflict-free for ldmatrix)

// ---------------- static device scratch (no runtime alloc allowed) ----------------
__device__ float g_qkvs[(size_t)Nn * 512];   // per layer: [q | k | v | x_r] each 128
__device__ float g_outb[(size_t)Nn * 128];   // attention output / gated output
__device__ float g_xcur[(size_t)Nn * 128];   // current node features (post layer)
__device__ float g_alpha[(size_t)Ee * 4];    // per-edge per-head exp weights (CSR order)
__device__ float g_bnsum[128];
__device__ float g_bnsq[128];
__device__ float g_bnsc[128];
__device__ float g_bnsh[128];
__device__ int   g_esrc[Ee];
__device__ int   g_edst[Ee];
__device__ int   g_batch[Nn];
__device__ float g_gsum[Gg * 128];
__device__ float g_gcnt[Gg];
__device__ int   g_flags[2];
// CSR by destination
__device__ int   g_deg[Nn];
__device__ int   g_rowptr[Nn + 1];
__device__ int   g_workoff[Nn];
__device__ int   g_csrc[Ee];
__device__ float2 g_cea[Ee];
// W split+transpose staging: [l*4+mat][n][k] bf16 hi/lo, unswizzled
__device__ __nv_bfloat16 g_Whi[12 * 16384];
__device__ __nv_bfloat16 g_Wlo[12 * 16384];

// ---------------- helpers ----------------
__device__ __forceinline__ uint32_t smem_u32(const void* p) {
    uint32_t a;
    asm("{ .reg .u64 t; cvta.to.shared.u64 t, %1; cvt.u32.u64 %0, t; }" : "=r"(a) : "l"(p));
    return a;
}

// ---------------- dtype sniffing: int64 vs int32 index tensors ----------------
__global__ void k_detect(const void* ei, const void* ba) {
    if (threadIdx.x == 0 && blockIdx.x == 0) {
        const unsigned int* p = (const unsigned int*)ei;
        unsigned int acc = 0;
        long long half_e = (long long)Ee - 1;
        for (int j = 0; j < 64; j++) {
            long long i = half_e * j / 63;
            acc |= p[2 * i + 1];
        }
        g_flags[0] = (acc == 0) ? 1 : 0;
        const unsigned int* q = (const unsigned int*)ba;
        unsigned int acc2 = 0;
        long long half_n = (long long)Nn / 2 - 1;
        for (int j = 0; j < 64; j++) {
            long long i = half_n * j / 63;
            acc2 |= q[2 * i + 1];
        }
        g_flags[1] = (acc2 == 0) ? 1 : 0;
    }
}

__global__ void k_convert(const void* ei, const void* ba) {
    int i = blockIdx.x * blockDim.x + threadIdx.x;
    int f0 = g_flags[0], f1 = g_flags[1];
    if (i < 2 * Ee) {
        int v = f0 ? (int)((const long long*)ei)[i] : ((const int*)ei)[i];
        if (i < Ee) g_esrc[i] = v;
        else        g_edst[i - Ee] = v;
    }
    if (i < Nn) {
        g_batch[i] = f1 ? (int)((const long long*)ba)[i] : ((const int*)ba)[i];
    }
}

// ---------------- CSR build ----------------
__global__ void k_zerodeg() {
    int i = blockIdx.x * blockDim.x + threadIdx.x;
    if (i < Nn) g_deg[i] = 0;
}
__global__ void k_hist() {
    int i = blockIdx.x * blockDim.x + threadIdx.x;
    if (i < Ee) atomicAdd(&g_deg[g_edst[i]], 1);
}
__global__ void __launch_bounds__(1024) k_scan() {
    __shared__ int sm[1024];
    int tid = threadIdx.x;
    int run = 0;
    for (int base = 0; base < Nn; base += 1024) {
        int i = base + tid;
        int v = (i < Nn) ? g_deg[i] : 0;
        sm[tid] = v;
        __syncthreads();
        for (int off = 1; off < 1024; off <<= 1) {
            int t = (tid >= off) ? sm[tid - off] : 0;
            __syncthreads();
            sm[tid] += t;
            __syncthreads();
        }
        if (i < Nn) g_rowptr[i] = run + sm[tid] - v;   // exclusive
        run += sm[1023];
        __syncthreads();
    }
    if (tid == 0) g_rowptr[Nn] = run;
}
__global__ void k_copyoff() {
    int i = blockIdx.x * blockDim.x + threadIdx.x;
    if (i < Nn) g_workoff[i] = g_rowptr[i];
}
__global__ void k_scatter(const float* __restrict__ edge_attr) {
    int i = blockIdx.x * blockDim.x + threadIdx.x;
    if (i >= Ee) return;
    int dst = g_edst[i];
    int pos = atomicAdd(&g_workoff[dst], 1);
    g_csrc[pos] = g_esrc[i];
    g_cea[pos] = make_float2(edge_attr[i * 2 + 0], edge_attr[i * 2 + 1]);
}

// ---------------- W split + transpose (12 mats, once per launch) --------------
// staging[j][k] = W[k][j]  (mma B operand wants [N,K] row-major)
__global__ void k_splitW(const float* __restrict__ Wq, const float* __restrict__ Wk,
                         const float* __restrict__ Wv, const float* __restrict__ Ws) {
    int i = blockIdx.x * blockDim.x + threadIdx.x;   // over 12*2048 chunks of 8
    if (i >= 12 * 2048) return;
    int lm = i >> 11;
    int cidx = i & 2047;
    int j = cidx >> 4;          // output col / B row
    int kc = cidx & 15;         // k chunk of 8
    int l = lm >> 2, mat = lm & 3;
    const float* W = (mat == 0 ? Wq : mat == 1 ? Wk : mat == 2 ? Wv : Ws)
                   + (size_t)l * 16384;
    __nv_bfloat16 hi[8], lo[8];
    #pragma unroll
    for (int s = 0; s < 8; s++) {
        float v = W[(kc * 8 + s) * 128 + j];
        hi[s] = __float2bfloat16(v);
        lo[s] = __float2bfloat16(v - __bfloat162float(hi[s]));
    }
    size_t base = (size_t)lm * 16384 + j * 128 + kc * 8;
    *(uint4*)(g_Whi + base) = *(uint4*)hi;
    *(uint4*)(g_Wlo + base) = *(uint4*)lo;
}

// ---------------- warp-MMA GEMM: 128x128x128 tile, bf16x3 emulated fp32 --------
// grid (TILES, 4 mats), 256 threads. dyn smem: Ahi|Alo|Whi|Wlo, 128x136 bf16 each.
#define SM_AHI 0
#define SM_ALO (128 * PADK * 2)
#define SM_WHI (2 * 128 * PADK * 2)
#define SM_WLO (3 * 128 * PADK * 2)
#define SM_TOT (4 * 128 * PADK * 2)

__global__ void __launch_bounds__(256) k_gemm_mma(
    const float* __restrict__ Asrc,  // nullptr -> g_xcur
    int l, const float* __restrict__ bq, const float* __restrict__ bk,
    const float* __restrict__ bv, const float* __restrict__ bs)
{
    extern __shared__ __align__(16) char sm[];
    int tid = threadIdx.x;
    int t = blockIdx.x, mat = blockIdx.y;
    const float* Ap = Asrc ? Asrc : g_xcur;

    // ---- load & split A: thread handles (row, 64-col half) ----
    {
        int r = tid >> 1, hf = tid & 1;
        int row = t * 128 + r;
        __nv_bfloat16* dhi = (__nv_bfloat16*)(sm + SM_AHI) + r * PADK + hf * 64;
        __nv_bfloat16* dlo = (__nv_bfloat16*)(sm + SM_ALO) + r * PADK + hf * 64;
        if (row < Nn) {
            const float4* src = (const float4*)(Ap + (size_t)row * 128 + hf * 64);
            #pragma unroll
            for (int c = 0; c < 8; c++) {   // 8 chunks of 8 floats
                float4 v0 = src[c * 2], v1 = src[c * 2 + 1];
                float vs[8] = {v0.x, v0.y, v0.z, v0.w, v1.x, v1.y, v1.z, v1.w};
                __nv_bfloat16 hi[8], lo[8];
                #pragma unroll
                for (int s = 0; s < 8; s++) {
                    hi[s] = __float2bfloat16(vs[s]);
                    lo[s] = __float2bfloat16(vs[s] - __bfloat162float(hi[s]));
                }
                *(uint4*)(dhi + c * 8) = *(uint4*)hi;
                *(uint4*)(dlo + c * 8) = *(uint4*)lo;
            }
        } else {
            uint4 z = make_uint4(0, 0, 0, 0);
            #pragma unroll
            for (int c = 0; c < 8; c++) {
                *(uint4*)(dhi + c * 8) = z;
                *(uint4*)(dlo + c * 8) = z;
            }
        }
    }
    // ---- load W hi/lo from staging ----
    {
        int n = tid >> 1, hf = tid & 1;
        size_t base = (size_t)(l * 4 + mat) * 16384 + n * 128 + hf * 64;
        const uint4* shi = (const uint4*)(g_Whi + base);
        const uint4* slo = (const uint4*)(g_Wlo + base);
        uint4* dhi = (uint4*)((__nv_bfloat16*)(sm + SM_WHI) + n * PADK + hf * 64);
        uint4* dlo = (uint4*)((__nv_bfloat16*)(sm + SM_WLO) + n * PADK + hf * 64);
        #pragma unroll
        for (int c = 0; c < 8; c++) { dhi[c] = shi[c]; dlo[c] = slo[c]; }
    }
    __syncthreads();

    int wid = tid >> 5, lane = tid & 31;
    int wr = wid >> 1, wc = wid & 1;       // warp tile: rows wr*32, cols wc*64
    int m0 = wr * 32, n0 = wc * 64;

    // ldmatrix lane addressing
    int quad = lane >> 3, qr = lane & 7;
    int a_row = ((quad & 1) << 3) + qr;    // 0..15
    int a_kof = (quad & 2) << 2;           // 0 or 8
    int b_row = qr;
    int b_kof = (quad & 1) << 3;           // x2 uses lanes 0..15

    uint32_t sb = smem_u32(sm);
    uint32_t aBase[2];                     // per pass A source (hi, hi, lo)
    aBase[0] = sb + SM_AHI;
    aBase[1] = sb + SM_ALO;
    uint32_t wBase[2];
    wBase[0] = sb + SM_WHI;
    wBase[1] = sb + SM_WLO;

    float acc[2][8][4];
    #pragma unroll
    for (int mt = 0; mt < 2; mt++)
        #pragma unroll
        for (int nt = 0; nt < 8; nt++)
            #pragma unroll
            for (int c = 0; c < 4; c++) acc[mt][nt][c] = 0.0f;

    #pragma unroll
    for (int pass = 0; pass < 3; pass++) {
        uint32_t ab = aBase[pass == 2 ? 1 : 0];
        uint32_t wb = wBase[pass == 1 ? 1 : 0];
        #pragma unroll
        for (int ks = 0; ks < 8; ks++) {
            int k0 = ks * 16;
            uint32_t af[2][4];
            #pragma unroll
            for (int mt = 0; mt < 2; mt++) {
                uint32_t addr = ab + ((m0 + mt * 16 + a_row) * PADK + k0 + a_kof) * 2;
                asm volatile("ldmatrix.sync.aligned.m8n8.x4.shared.b16 {%0,%1,%2,%3}, [%4];"
                             : "=r"(af[mt][0]), "=r"(af[mt][1]), "=r"(af[mt][2]), "=r"(af[mt][3])
                             : "r"(addr));
            }
            #pragma unroll
            for (int nt = 0; nt < 8; nt++) {
                uint32_t bf[2];
                uint32_t addr = wb + ((n0 + nt * 8 + b_row) * PADK + k0 + b_kof) * 2;
                asm volatile("ldmatrix.sync.aligned.m8n8.x2.shared.b16 {%0,%1}, [%2];"
                             : "=r"(bf[0]), "=r"(bf[1]) : "r"(addr));
                #pragma unroll
                for (int mt = 0; mt < 2; mt++) {
                    asm volatile(
                        "mma.sync.aligned.m16n8k16.row.col.f32.bf16.bf16.f32 "
                        "{%0,%1,%2,%3}, {%4,%5,%6,%7}, {%8,%9}, {%0,%1,%2,%3};"
                        : "+f"(acc[mt][nt][0]), "+f"(acc[mt][nt][1]),
                          "+f"(acc[mt][nt][2]), "+f"(acc[mt][nt][3])
                        : "r"(af[mt][0]), "r"(af[mt][1]), "r"(af[mt][2]), "r"(af[mt][3]),
                          "r"(bf[0]), "r"(bf[1]));
                }
            }
        }
    }

    // ---- epilogue ----
    const float* bias = (mat == 0 ? bq : mat == 1 ? bk : mat == 2 ? bv : bs) + l * 128;
    int drow = lane >> 2, dcol = (lane & 3) * 2;
    #pragma unroll
    for (int mt = 0; mt < 2; mt++) {
        #pragma unroll
        for (int nt = 0; nt < 8; nt++) {
            int col = n0 + nt * 8 + dcol;
            float b0 = bias[col], b1 = bias[col + 1];
            int r0 = t * 128 + m0 + mt * 16 + drow;
            if (r0 < Nn) {
                float2 v = {acc[mt][nt][0] + b0, acc[mt][nt][1] + b1};
                *(float2*)(g_qkvs + (size_t)r0 * 512 + mat * 128 + col) = v;
            }
            int r1 = r0 + 8;
            if (r1 < Nn) {
                float2 v = {acc[mt][nt][2] + b0, acc[mt][nt][3] + b1};
                *(float2*)(g_qkvs + (size_t)r1 * 512 + mat * 128 + col) = v;
            }
        }
    }
}

// ---------------- fused edge phase: warp per destination node -------------------
// loop1: logits -> exp -> den (registers); loop2: weighted message accumulate.
// No atomics, no init pass. Softmax computed without max-shift (logits are O(1);
// ratio is shift-invariant so result matches reference to fp32 accuracy).
__global__ void __launch_bounds__(256) k_edge(const float* __restrict__ We,
                                              const float* __restrict__ be)
{
    int n = (blockIdx.x * blockDim.x + threadIdx.x) >> 5;
    int lane = threadIdx.x & 31;
    if (n >= Nn) return;
    int s = g_rowptr[n], eend = g_rowptr[n + 1];

    float4 qv = ((const float4*)(g_qkvs + (size_t)n * 512))[lane];
    float4 w0 = ((const float4*)We)[lane];
    float4 w1 = ((const float4*)(We + 128))[lane];
    float4 bb = ((const float4*)be)[lane];
    int h = lane >> 3;

    float den = 0.0f;
    for (int e = s; e < eend; e++) {
        int src = g_csrc[e];
        float2 a = g_cea[e];
        float4 kv = ((const float4*)(g_qkvs + (size_t)src * 512 + 128))[lane];
        float d = qv.x * (kv.x + fmaf(a.x, w0.x, fmaf(a.y, w1.x, bb.x)))
                + qv.y * (kv.y + fmaf(a.x, w0.y, fmaf(a.y, w1.y, bb.y)))
                + qv.z * (kv.z + fmaf(a.x, w0.z, fmaf(a.y, w1.z, bb.z)))
                + qv.w * (kv.w + fmaf(a.x, w0.w, fmaf(a.y, w1.w, bb.w)));
        d += __shfl_xor_sync(0xffffffffu, d, 4);
        d += __shfl_xor_sync(0xffffffffu, d, 2);
        d += __shfl_xor_sync(0xffffffffu, d, 1);
        float ex = expf(d * 0.17677669529663687f);  // 1/sqrt(32)
        den += ex;
        if ((lane & 7) == 0) g_alpha[(size_t)e * 4 + h] = ex;
    }
    float inv = 1.0f / (den + 1e-16f);

    float4 msg = make_float4(0.f, 0.f, 0.f, 0.f);
    for (int e = s; e < eend; e++) {
        int src = g_csrc[e];
        float2 a = g_cea[e];
        float w = g_alpha[(size_t)e * 4 + h] * inv;
        float4 vv = ((const float4*)(g_qkvs + (size_t)src * 512 + 256))[lane];
        msg.x += (vv.x + fmaf(a.x, w0.x, fmaf(a.y, w1.x, bb.x))) * w;
        msg.y += (vv.y + fmaf(a.x, w0.y, fmaf(a.y, w1.y, bb.y))) * w;
        msg.z += (vv.z + fmaf(a.x, w0.z, fmaf(a.y, w1.z, bb.z))) * w;
        msg.w += (vv.w + fmaf(a.x, w0.w, fmaf(a.y, w1.w, bb.w))) * w;
    }
    ((float4*)(g_outb + (size_t)n * 128))[lane] = msg;
}

// ---------------- BN accumulator zero (per layer) ----------------
__global__ void k_zerobn() {
    int c = threadIdx.x;
    if (c < 128) { g_bnsum[c] = 0.0f; g_bnsq[c] = 0.0f; }
}

// ---------------- beta gate + BN partial stats (warp per node, 8 nodes/block) ----
__global__ void k_gate(const float* __restrict__ Wbeta) {
    __shared__ float ssum[128];
    __shared__ float ssq[128];
    int tid = threadIdx.x;
    if (tid < 128) { ssum[tid] = 0.0f; ssq[tid] = 0.0f; }
    __syncthreads();
    int lane = tid & 31;
    int n = blockIdx.x * 8 + (tid >> 5);
    if (n < Nn) {
        float4 o = ((const float4*)(g_outb + (size_t)n * 128))[lane];
        float4 xr = ((const float4*)(g_qkvs + (size_t)n * 512 + 384))[lane];
        float4 w1 = ((const float4*)Wbeta)[lane];
        float4 w2 = ((const float4*)(Wbeta + 128))[lane];
        float4 w3 = ((const float4*)(Wbeta + 256))[lane];
        float s = o.x * w1.x + o.y * w1.y + o.z * w1.z + o.w * w1.w
                + xr.x * w2.x + xr.y * w2.y + xr.z * w2.z + xr.w * w2.w
                + (o.x - xr.x) * w3.x + (o.y - xr.y) * w3.y
                + (o.z - xr.z) * w3.z + (o.w - xr.w) * w3.w;
        #pragma unroll
        for (int m = 16; m > 0; m >>= 1) s += __shfl_xor_sync(0xffffffffu, s, m);
        float g = 1.0f / (1.0f + expf(-s));
        float4 no;
        no.x = g * xr.x + (1.0f - g) * o.x;
        no.y = g * xr.y + (1.0f - g) * o.y;
        no.z = g * xr.z + (1.0f - g) * o.z;
        no.w = g * xr.w + (1.0f - g) * o.w;
        ((float4*)(g_outb + (size_t)n * 128))[lane] = no;
        int c = lane * 4;
        atomicAdd(&ssum[c + 0], no.x); atomicAdd(&ssq[c + 0], no.x * no.x);
        atomicAdd(&ssum[c + 1], no.y); atomicAdd(&ssq[c + 1], no.y * no.y);
        atomicAdd(&ssum[c + 2], no.z); atomicAdd(&ssq[c + 2], no.z * no.z);
        atomicAdd(&ssum[c + 3], no.w); atomicAdd(&ssq[c + 3], no.w * no.w);
    }
    __syncthreads();
    if (tid < 128) {
        atomicAdd(&g_bnsum[tid], ssum[tid]);
        atomicAdd(&g_bnsq[tid], ssq[tid]);
    }
}

// ---------------- BN finalize ----------------
__global__ void k_bnstats(const float* __restrict__ gamma, const float* __restrict__ beta) {
    int c = threadIdx.x;
    if (c < 128) {
        float mu = g_bnsum[c] / (float)Nn;
        float var = g_bnsq[c] / (float)Nn - mu * mu;
        float rs = rsqrtf(var + 1e-5f);
        float sc = gamma[c] * rs;
        g_bnsc[c] = sc;
        g_bnsh[c] = beta[c] - mu * sc;
    }
}

// ---------------- BN apply + ELU ----------------
__global__ void k_bnelu() {
    int i = blockIdx.x * blockDim.x + threadIdx.x;
    if (i >= Nn * 128) return;
    int c = i & 127;
    float y = g_outb[i] * g_bnsc[c] + g_bnsh[c];
    g_xcur[i] = y > 0.0f ? y : expm1f(y);
}

// ---------------- readout ----------------
__global__ void k_poolinit() {
    int i = blockIdx.x * blockDim.x + threadIdx.x;
    if (i < Gg * 128) g_gsum[i] = 0.0f;
    if (i < Gg) g_gcnt[i] = 0.0f;
}

__global__ void k_pool() {
    int wid = (blockIdx.x * blockDim.x + threadIdx.x) >> 5;
    int lane = threadIdx.x & 31;
    if (wid >= Nn) return;
    int b = g_batch[wid];
    float4 v = ((const float4*)(g_xcur + (size_t)wid * 128))[lane];
    float* o = g_gsum + b * 128 + lane * 4;
    atomicAdd(o + 0, v.x);
    atomicAdd(o + 1, v.y);
    atomicAdd(o + 2, v.z);
    atomicAdd(o + 3, v.w);
    if (lane == 0) atomicAdd(&g_gcnt[b], 1.0f);
}

__global__ void k_read(const float* __restrict__ Wout, const float* __restrict__ bout,
                       const float* __restrict__ obias, float* __restrict__ out) {
    __shared__ float red[128];
    int g = blockIdx.x;
    int c = threadIdx.x;
    float cnt = g_gcnt[g];
    float d = fmaxf(cnt, 1.0f);
    red[c] = g_gsum[g * 128 + c] / d * Wout[c];
    __syncthreads();
    for (int s = 64; s > 0; s >>= 1) {
        if (c < s) red[c] += red[c + s];
        __syncthreads();
    }
    if (c == 0) out[g] = red[0] + bout[0] + obias[0];
}

// ---------------- host ----------------
extern "C" void kernel_launch(void* const* d_in, const int* in_sizes, int n_in,
                              void* d_out, int out_size) {
    const float* x    = (const float*)d_in[0];
    const void*  ei   = d_in[1];
    const float* ea   = (const float*)d_in[2];
    const void*  ba   = d_in[3];
    const float* Wq   = (const float*)d_in[4];
    const float* bq   = (const float*)d_in[5];
    const float* Wk   = (const float*)d_in[6];
    const float* bk   = (const float*)d_in[7];
    const float* Wv   = (const float*)d_in[8];
    const float* bv   = (const float*)d_in[9];
    const float* We   = (const float*)d_in[10];
    const float* be   = (const float*)d_in[11];
    const float* Ws   = (const float*)d_in[12];
    const float* bs   = (const float*)d_in[13];
    const float* Wb   = (const float*)d_in[14];
    const float* gam  = (const float*)d_in[15];
    const float* bet  = (const float*)d_in[16];
    const float* Wout = (const float*)d_in[17];
    const float* bout = (const float*)d_in[18];
    const float* obia = (const float*)d_in[19];

    static int smem_set = 0;
    if (!smem_set) {
        cudaFuncSetAttribute(k_gemm_mma, cudaFuncAttributeMaxDynamicSharedMemorySize, SM_TOT);
        smem_set = 1;
    }

    k_detect<<<1, 32>>>(ei, ba);
    k_convert<<<(2 * Ee + 255) / 256, 256>>>(ei, ba);
    k_splitW<<<(12 * 2048 + 255) / 256, 256>>>(Wq, Wk, Wv, Ws);
    // CSR build (once; edges fixed across layers)
    k_zerodeg<<<(Nn + 255) / 256, 256>>>();
    k_hist<<<(Ee + 255) / 256, 256>>>();
    k_scan<<<1, 1024>>>();
    k_copyoff<<<(Nn + 255) / 256, 256>>>();
    k_scatter<<<(Ee + 255) / 256, 256>>>(ea);

    for (int l = 0; l < Lr; l++) {
        k_gemm_mma<<<dim3(TILES, 4), 256, SM_TOT>>>(
            l == 0 ? x : nullptr, l, bq, bk, bv, bs);
        k_edge<<<(Nn * 32 + 255) / 256, 256>>>(We + l * 256, be + l * 128);
        k_zerobn<<<1, 128>>>();
        k_gate<<<(Nn + 7) / 8, 256>>>(Wb + l * 384);
        k_bnstats<<<1, 128>>>(gam + l * 128, bet + l * 128);
        k_bnelu<<<(Nn * 128 + 255) / 256, 256>>>();
    }

    k_poolinit<<<(Gg * 128 + 255) / 256, 256>>>();
    k_pool<<<(Nn * 32 + 255) / 256, 256>>>();
    k_read<<<Gg, 128>>>(Wout, bout, obia, (float*)d_out);
}

// round 8
// speedup vs baseline: 1.7803x; 1.0415x over previous
#include <cuda_runtime.h>
#include <cuda_bf16.h>
#include <math.h>
#include <stdint.h>

#define Nn 50000
#define Ee 800000
#define Gg 50
#define Lr 3
#define TILES 391            // ceil(50000/128)
#define PADK 136             // smem row stride in bf16 (272B, conflict-free for ldmatrix)

// ---------------- static device scratch (no runtime alloc allowed) ----------------
__device__ float g_qkvs[(size_t)Nn * 512];   // per layer: [q | (unused) | (unused) | x_r]
__device__ __nv_bfloat16 g_kv16[(size_t)Nn * 256];  // packed bf16 [k(128) | v(128)] per node
__device__ float g_outb[(size_t)Nn * 128];   // attention output / gated output
__device__ float g_xcur[(size_t)Nn * 128];   // current node features (post layer)
__device__ float g_alpha[(size_t)Ee * 4];    // per-edge per-head exp weights (CSR order)
__device__ float g_bnsum[128];
__device__ float g_bnsq[128];
__device__ float g_bnsc[128];
__device__ float g_bnsh[128];
__device__ int   g_esrc[Ee];
__device__ int   g_edst[Ee];
__device__ int   g_batch[Nn];
__device__ float g_gsum[Gg * 128];
__device__ float g_gcnt[Gg];
__device__ int   g_flags[2];
// CSR by destination
__device__ int   g_deg[Nn];
__device__ int   g_rowptr[Nn + 1];
__device__ int   g_workoff[Nn];
__device__ int   g_csrc[Ee];
__device__ float2 g_cea[Ee];
// W split+transpose staging: [l*4+mat][n][k] bf16 hi/lo, unswizzled
__device__ __nv_bfloat16 g_Whi[12 * 16384];
__device__ __nv_bfloat16 g_Wlo[12 * 16384];

// ---------------- helpers ----------------
__device__ __forceinline__ uint32_t smem_u32(const void* p) {
    uint32_t a;
    asm("{ .reg .u64 t; cvta.to.shared.u64 t, %1; cvt.u32.u64 %0, t; }" : "=r"(a) : "l"(p));
    return a;
}

// ---------------- dtype sniffing: int64 vs int32 index tensors ----------------
__global__ void k_detect(const void* ei, const void* ba) {
    if (threadIdx.x == 0 && blockIdx.x == 0) {
        const unsigned int* p = (const unsigned int*)ei;
        unsigned int acc = 0;
        long long half_e = (long long)Ee - 1;
        for (int j = 0; j < 64; j++) {
            long long i = half_e * j / 63;
            acc |= p[2 * i + 1];
        }
        g_flags[0] = (acc == 0) ? 1 : 0;
        const unsigned int* q = (const unsigned int*)ba;
        unsigned int acc2 = 0;
        long long half_n = (long long)Nn / 2 - 1;
        for (int j = 0; j < 64; j++) {
            long long i = half_n * j / 63;
            acc2 |= q[2 * i + 1];
        }
        g_flags[1] = (acc2 == 0) ? 1 : 0;
    }
}

__global__ void k_convert(const void* ei, const void* ba) {
    int i = blockIdx.x * blockDim.x + threadIdx.x;
    int f0 = g_flags[0], f1 = g_flags[1];
    if (i < 2 * Ee) {
        int v = f0 ? (int)((const long long*)ei)[i] : ((const int*)ei)[i];
        if (i < Ee) g_esrc[i] = v;
        else        g_edst[i - Ee] = v;
    }
    if (i < Nn) {
        g_batch[i] = f1 ? (int)((const long long*)ba)[i] : ((const int*)ba)[i];
    }
}

// ---------------- CSR build ----------------
__global__ void k_zerodeg() {
    int i = blockIdx.x * blockDim.x + threadIdx.x;
    if (i < Nn) g_deg[i] = 0;
}
__global__ void k_hist() {
    int i = blockIdx.x * blockDim.x + threadIdx.x;
    if (i < Ee) atomicAdd(&g_deg[g_edst[i]], 1);
}
__global__ void __launch_bounds__(1024) k_scan() {
    __shared__ int sm[1024];
    int tid = threadIdx.x;
    int run = 0;
    for (int base = 0; base < Nn; base += 1024) {
        int i = base + tid;
        int v = (i < Nn) ? g_deg[i] : 0;
        sm[tid] = v;
        __syncthreads();
        for (int off = 1; off < 1024; off <<= 1) {
            int t = (tid >= off) ? sm[tid - off] : 0;
            __syncthreads();
            sm[tid] += t;
            __syncthreads();
        }
        if (i < Nn) g_rowptr[i] = run + sm[tid] - v;   // exclusive
        run += sm[1023];
        __syncthreads();
    }
    if (tid == 0) g_rowptr[Nn] = run;
}
__global__ void k_copyoff() {
    int i = blockIdx.x * blockDim.x + threadIdx.x;
    if (i < Nn) g_workoff[i] = g_rowptr[i];
}
__global__ void k_scatter(const float* __restrict__ edge_attr) {
    int i = blockIdx.x * blockDim.x + threadIdx.x;
    if (i >= Ee) return;
    int dst = g_edst[i];
    int pos = atomicAdd(&g_workoff[dst], 1);
    g_csrc[pos] = g_esrc[i];
    g_cea[pos] = make_float2(edge_attr[i * 2 + 0], edge_attr[i * 2 + 1]);
}

// ---------------- W split + transpose (12 mats, once per launch) --------------
__global__ void k_splitW(const float* __restrict__ Wq, const float* __restrict__ Wk,
                         const float* __restrict__ Wv, const float* __restrict__ Ws) {
    int i = blockIdx.x * blockDim.x + threadIdx.x;   // over 12*2048 chunks of 8
    if (i >= 12 * 2048) return;
    int lm = i >> 11;
    int cidx = i & 2047;
    int j = cidx >> 4;          // output col / B row
    int kc = cidx & 15;         // k chunk of 8
    int l = lm >> 2, mat = lm & 3;
    const float* W = (mat == 0 ? Wq : mat == 1 ? Wk : mat == 2 ? Wv : Ws)
                   + (size_t)l * 16384;
    __nv_bfloat16 hi[8], lo[8];
    #pragma unroll
    for (int s = 0; s < 8; s++) {
        float v = W[(kc * 8 + s) * 128 + j];
        hi[s] = __float2bfloat16(v);
        lo[s] = __float2bfloat16(v - __bfloat162float(hi[s]));
    }
    size_t base = (size_t)lm * 16384 + j * 128 + kc * 8;
    *(uint4*)(g_Whi + base) = *(uint4*)hi;
    *(uint4*)(g_Wlo + base) = *(uint4*)lo;
}

// ---------------- warp-MMA GEMM: 128x128x128 tile, bf16x3 emulated fp32 --------
#define SM_AHI 0
#define SM_ALO (128 * PADK * 2)
#define SM_WHI (2 * 128 * PADK * 2)
#define SM_WLO (3 * 128 * PADK * 2)
#define SM_TOT (4 * 128 * PADK * 2)

__global__ void __launch_bounds__(256) k_gemm_mma(
    const float* __restrict__ Asrc,  // nullptr -> g_xcur
    int l, const float* __restrict__ bq, const float* __restrict__ bk,
    const float* __restrict__ bv, const float* __restrict__ bs)
{
    extern __shared__ __align__(16) char sm[];
    int tid = threadIdx.x;
    int t = blockIdx.x, mat = blockIdx.y;
    const float* Ap = Asrc ? Asrc : g_xcur;

    // ---- load & split A ----
    {
        int r = tid >> 1, hf = tid & 1;
        int row = t * 128 + r;
        __nv_bfloat16* dhi = (__nv_bfloat16*)(sm + SM_AHI) + r * PADK + hf * 64;
        __nv_bfloat16* dlo = (__nv_bfloat16*)(sm + SM_ALO) + r * PADK + hf * 64;
        if (row < Nn) {
            const float4* src = (const float4*)(Ap + (size_t)row * 128 + hf * 64);
            #pragma unroll
            for (int c = 0; c < 8; c++) {
                float4 v0 = src[c * 2], v1 = src[c * 2 + 1];
                float vs[8] = {v0.x, v0.y, v0.z, v0.w, v1.x, v1.y, v1.z, v1.w};
                __nv_bfloat16 hi[8], lo[8];
                #pragma unroll
                for (int s = 0; s < 8; s++) {
                    hi[s] = __float2bfloat16(vs[s]);
                    lo[s] = __float2bfloat16(vs[s] - __bfloat162float(hi[s]));
                }
                *(uint4*)(dhi + c * 8) = *(uint4*)hi;
                *(uint4*)(dlo + c * 8) = *(uint4*)lo;
            }
        } else {
            uint4 z = make_uint4(0, 0, 0, 0);
            #pragma unroll
            for (int c = 0; c < 8; c++) {
                *(uint4*)(dhi + c * 8) = z;
                *(uint4*)(dlo + c * 8) = z;
            }
        }
    }
    // ---- load W hi/lo from staging ----
    {
        int n = tid >> 1, hf = tid & 1;
        size_t base = (size_t)(l * 4 + mat) * 16384 + n * 128 + hf * 64;
        const uint4* shi = (const uint4*)(g_Whi + base);
        const uint4* slo = (const uint4*)(g_Wlo + base);
        uint4* dhi = (uint4*)((__nv_bfloat16*)(sm + SM_WHI) + n * PADK + hf * 64);
        uint4* dlo = (uint4*)((__nv_bfloat16*)(sm + SM_WLO) + n * PADK + hf * 64);
        #pragma unroll
        for (int c = 0; c < 8; c++) { dhi[c] = shi[c]; dlo[c] = slo[c]; }
    }
    __syncthreads();

    int wid = tid >> 5, lane = tid & 31;
    int wr = wid >> 1, wc = wid & 1;
    int m0 = wr * 32, n0 = wc * 64;

    int quad = lane >> 3, qr = lane & 7;
    int a_row = ((quad & 1) << 3) + qr;
    int a_kof = (quad & 2) << 2;
    int b_row = qr;
    int b_kof = (quad & 1) << 3;

    uint32_t sb = smem_u32(sm);
    uint32_t aBase[2];
    aBase[0] = sb + SM_AHI;
    aBase[1] = sb + SM_ALO;
    uint32_t wBase[2];
    wBase[0] = sb + SM_WHI;
    wBase[1] = sb + SM_WLO;

    float acc[2][8][4];
    #pragma unroll
    for (int mt = 0; mt < 2; mt++)
        #pragma unroll
        for (int nt = 0; nt < 8; nt++)
            #pragma unroll
            for (int c = 0; c < 4; c++) acc[mt][nt][c] = 0.0f;

    #pragma unroll
    for (int pass = 0; pass < 3; pass++) {
        uint32_t ab = aBase[pass == 2 ? 1 : 0];
        uint32_t wb = wBase[pass == 1 ? 1 : 0];
        #pragma unroll
        for (int ks = 0; ks < 8; ks++) {
            int k0 = ks * 16;
            uint32_t af[2][4];
            #pragma unroll
            for (int mt = 0; mt < 2; mt++) {
                uint32_t addr = ab + ((m0 + mt * 16 + a_row) * PADK + k0 + a_kof) * 2;
                asm volatile("ldmatrix.sync.aligned.m8n8.x4.shared.b16 {%0,%1,%2,%3}, [%4];"
                             : "=r"(af[mt][0]), "=r"(af[mt][1]), "=r"(af[mt][2]), "=r"(af[mt][3])
                             : "r"(addr));
            }
            #pragma unroll
            for (int nt = 0; nt < 8; nt++) {
                uint32_t bf[2];
                uint32_t addr = wb + ((n0 + nt * 8 + b_row) * PADK + k0 + b_kof) * 2;
                asm volatile("ldmatrix.sync.aligned.m8n8.x2.shared.b16 {%0,%1}, [%2];"
                             : "=r"(bf[0]), "=r"(bf[1]) : "r"(addr));
                #pragma unroll
                for (int mt = 0; mt < 2; mt++) {
                    asm volatile(
                        "mma.sync.aligned.m16n8k16.row.col.f32.bf16.bf16.f32 "
                        "{%0,%1,%2,%3}, {%4,%5,%6,%7}, {%8,%9}, {%0,%1,%2,%3};"
                        : "+f"(acc[mt][nt][0]), "+f"(acc[mt][nt][1]),
                          "+f"(acc[mt][nt][2]), "+f"(acc[mt][nt][3])
                        : "r"(af[mt][0]), "r"(af[mt][1]), "r"(af[mt][2]), "r"(af[mt][3]),
                          "r"(bf[0]), "r"(bf[1]));
                }
            }
        }
    }

    // ---- epilogue: q/skip -> fp32 g_qkvs; k/v -> packed bf16 g_kv16 ----
    const float* bias = (mat == 0 ? bq : mat == 1 ? bk : mat == 2 ? bv : bs) + l * 128;
    int drow = lane >> 2, dcol = (lane & 3) * 2;
    int kvoff = (mat == 1) ? 0 : 128;     // valid when mat==1||2
    bool iskv = (mat == 1) || (mat == 2);
    #pragma unroll
    for (int mt = 0; mt < 2; mt++) {
        #pragma unroll
        for (int nt = 0; nt < 8; nt++) {
            int col = n0 + nt * 8 + dcol;
            float b0 = bias[col], b1 = bias[col + 1];
            int r0 = t * 128 + m0 + mt * 16 + drow;
            if (r0 < Nn) {
                float v0 = acc[mt][nt][0] + b0, v1 = acc[mt][nt][1] + b1;
                if (iskv) {
                    __nv_bfloat162 p = {__float2bfloat16(v0), __float2bfloat16(v1)};
                    *(__nv_bfloat162*)(g_kv16 + (size_t)r0 * 256 + kvoff + col) = p;
                } else {
                    *(float2*)(g_qkvs + (size_t)r0 * 512 + mat * 128 + col) =
                        make_float2(v0, v1);
                }
            }
            int r1 = r0 + 8;
            if (r1 < Nn) {
                float v0 = acc[mt][nt][2] + b0, v1 = acc[mt][nt][3] + b1;
                if (iskv) {
                    __nv_bfloat162 p = {__float2bfloat16(v0), __float2bfloat16(v1)};
                    *(__nv_bfloat162*)(g_kv16 + (size_t)r1 * 256 + kvoff + col) = p;
                } else {
                    *(float2*)(g_qkvs + (size_t)r1 * 512 + mat * 128 + col) =
                        make_float2(v0, v1);
                }
            }
        }
    }
}

// ---------------- fused edge phase: warp per destination node -------------------
// bf16 k/v gathers (256B each); edge-embedding folded algebraically:
//   logit = scale*q.k + a0*t0 + a1*t1 + tb    (t* = per-head scale*q.We dots)
//   msg   = sum(w*v) + (S0*inv)*We0 + (S1*inv)*We1 + (den*inv)*be
__global__ void __launch_bounds__(256) k_edge(const float* __restrict__ We,
                                              const float* __restrict__ be)
{
    int n = (blockIdx.x * blockDim.x + threadIdx.x) >> 5;
    int lane = threadIdx.x & 31;
    if (n >= Nn) return;
    int s = g_rowptr[n], eend = g_rowptr[n + 1];

    float4 qv = ((const float4*)(g_qkvs + (size_t)n * 512))[lane];
    float4 w0 = ((const float4*)We)[lane];
    float4 w1 = ((const float4*)(We + 128))[lane];
    float4 bb = ((const float4*)be)[lane];
    int h = lane >> 3;
    const float scale = 0.17677669529663687f;   // 1/sqrt(32)

    // per-head projections of q onto We rows and be (broadcast within head)
    float p0 = qv.x * w0.x + qv.y * w0.y + qv.z * w0.z + qv.w * w0.w;
    float p1 = qv.x * w1.x + qv.y * w1.y + qv.z * w1.z + qv.w * w1.w;
    float pb = qv.x * bb.x + qv.y * bb.y + qv.z * bb.z + qv.w * bb.w;
    #pragma unroll
    for (int m = 4; m > 0; m >>= 1) {
        p0 += __shfl_xor_sync(0xffffffffu, p0, m);
        p1 += __shfl_xor_sync(0xffffffffu, p1, m);
        pb += __shfl_xor_sync(0xffffffffu, pb, m);
    }
    float t0 = p0 * scale, t1 = p1 * scale, tb = pb * scale;

    float den = 0.0f, S0 = 0.0f, S1 = 0.0f;
    for (int e = s; e < eend; e++) {
        int src = g_csrc[e];
        float2 a = g_cea[e];
        // k: 4 bf16 per lane (8B), 256B per warp
        uint2 kr = *(const uint2*)(g_kv16 + (size_t)src * 256 + lane * 4);
        float2 k0 = __bfloat1622float2(*(__nv_bfloat162*)&kr.x);
        float2 k1 = __bfloat1622float2(*(__nv_bfloat162*)&kr.y);
        float d = qv.x * k0.x + qv.y * k0.y + qv.z * k1.x + qv.w * k1.y;
        d += __shfl_xor_sync(0xffffffffu, d, 4);
        d += __shfl_xor_sync(0xffffffffu, d, 2);
        d += __shfl_xor_sync(0xffffffffu, d, 1);
        float logit = fmaf(d, scale, fmaf(a.x, t0, fmaf(a.y, t1, tb)));
        float ex = expf(logit);
        den += ex;
        S0 = fmaf(ex, a.x, S0);
        S1 = fmaf(ex, a.y, S1);
        if ((lane & 7) == 0) g_alpha[(size_t)e * 4 + h] = ex;
    }
    float inv = 1.0f / (den + 1e-16f);
    float c0 = S0 * inv, c1 = S1 * inv, cb = den * inv;

    float4 msg;
    msg.x = fmaf(c0, w0.x, fmaf(c1, w1.x, cb * bb.x));
    msg.y = fmaf(c0, w0.y, fmaf(c1, w1.y, cb * bb.y));
    msg.z = fmaf(c0, w0.z, fmaf(c1, w1.z, cb * bb.z));
    msg.w = fmaf(c0, w0.w, fmaf(c1, w1.w, cb * bb.w));
    for (int e = s; e < eend; e++) {
        int src = g_csrc[e];
        float w = g_alpha[(size_t)e * 4 + h] * inv;
        uint2 vr = *(const uint2*)(g_kv16 + (size_t)src * 256 + 128 + lane * 4);
        float2 v0 = __bfloat1622float2(*(__nv_bfloat162*)&vr.x);
        float2 v1 = __bfloat1622float2(*(__nv_bfloat162*)&vr.y);
        msg.x = fmaf(w, v0.x, msg.x);
        msg.y = fmaf(w, v0.y, msg.y);
        msg.z = fmaf(w, v1.x, msg.z);
        msg.w = fmaf(w, v1.y, msg.w);
    }
    ((float4*)(g_outb + (size_t)n * 128))[lane] = msg;
}

// ---------------- BN accumulator zero (per layer) ----------------
__global__ void k_zerobn() {
    int c = threadIdx.x;
    if (c < 128) { g_bnsum[c] = 0.0f; g_bnsq[c] = 0.0f; }
}

// ---------------- beta gate + BN partial stats (warp per node, 8 nodes/block) ----
__global__ void k_gate(const float* __restrict__ Wbeta) {
    __shared__ float ssum[128];
    __shared__ float ssq[128];
    int tid = threadIdx.x;
    if (tid < 128) { ssum[tid] = 0.0f; ssq[tid] = 0.0f; }
    __syncthreads();
    int lane = tid & 31;
    int n = blockIdx.x * 8 + (tid >> 5);
    if (n < Nn) {
        float4 o = ((const float4*)(g_outb + (size_t)n * 128))[lane];
        float4 xr = ((const float4*)(g_qkvs + (size_t)n * 512 + 384))[lane];
        float4 w1 = ((const float4*)Wbeta)[lane];
        float4 w2 = ((const float4*)(Wbeta + 128))[lane];
        float4 w3 = ((const float4*)(Wbeta + 256))[lane];
        float s = o.x * w1.x + o.y * w1.y + o.z * w1.z + o.w * w1.w
                + xr.x * w2.x + xr.y * w2.y + xr.z * w2.z + xr.w * w2.w
                + (o.x - xr.x) * w3.x + (o.y - xr.y) * w3.y
                + (o.z - xr.z) * w3.z + (o.w - xr.w) * w3.w;
        #pragma unroll
        for (int m = 16; m > 0; m >>= 1) s += __shfl_xor_sync(0xffffffffu, s, m);
        float g = 1.0f / (1.0f + expf(-s));
        float4 no;
        no.x = g * xr.x + (1.0f - g) * o.x;
        no.y = g * xr.y + (1.0f - g) * o.y;
        no.z = g * xr.z + (1.0f - g) * o.z;
        no.w = g * xr.w + (1.0f - g) * o.w;
        ((float4*)(g_outb + (size_t)n * 128))[lane] = no;
        int c = lane * 4;
        atomicAdd(&ssum[c + 0], no.x); atomicAdd(&ssq[c + 0], no.x * no.x);
        atomicAdd(&ssum[c + 1], no.y); atomicAdd(&ssq[c + 1], no.y * no.y);
        atomicAdd(&ssum[c + 2], no.z); atomicAdd(&ssq[c + 2], no.z * no.z);
        atomicAdd(&ssum[c + 3], no.w); atomicAdd(&ssq[c + 3], no.w * no.w);
    }
    __syncthreads();
    if (tid < 128) {
        atomicAdd(&g_bnsum[tid], ssum[tid]);
        atomicAdd(&g_bnsq[tid], ssq[tid]);
    }
}

// ---------------- BN finalize ----------------
__global__ void k_bnstats(const float* __restrict__ gamma, const float* __restrict__ beta) {
    int c = threadIdx.x;
    if (c < 128) {
        float mu = g_bnsum[c] / (float)Nn;
        float var = g_bnsq[c] / (float)Nn - mu * mu;
        float rs = rsqrtf(var + 1e-5f);
        float sc = gamma[c] * rs;
        g_bnsc[c] = sc;
        g_bnsh[c] = beta[c] - mu * sc;
    }
}

// ---------------- BN apply + ELU ----------------
__global__ void k_bnelu() {
    int i = blockIdx.x * blockDim.x + threadIdx.x;
    if (i >= Nn * 128) return;
    int c = i & 127;
    float y = g_outb[i] * g_bnsc[c] + g_bnsh[c];
    g_xcur[i] = y > 0.0f ? y : expm1f(y);
}

// ---------------- readout ----------------
__global__ void k_poolinit() {
    int i = blockIdx.x * blockDim.x + threadIdx.x;
    if (i < Gg * 128) g_gsum[i] = 0.0f;
    if (i < Gg) g_gcnt[i] = 0.0f;
}

__global__ void k_pool() {
    int wid = (blockIdx.x * blockDim.x + threadIdx.x) >> 5;
    int lane = threadIdx.x & 31;
    if (wid >= Nn) return;
    int b = g_batch[wid];
    float4 v = ((const float4*)(g_xcur + (size_t)wid * 128))[lane];
    float* o = g_gsum + b * 128 + lane * 4;
    atomicAdd(o + 0, v.x);
    atomicAdd(o + 1, v.y);
    atomicAdd(o + 2, v.z);
    atomicAdd(o + 3, v.w);
    if (lane == 0) atomicAdd(&g_gcnt[b], 1.0f);
}

__global__ void k_read(const float* __restrict__ Wout, const float* __restrict__ bout,
                       const float* __restrict__ obias, float* __restrict__ out) {
    __shared__ float red[128];
    int g = blockIdx.x;
    int c = threadIdx.x;
    float cnt = g_gcnt[g];
    float d = fmaxf(cnt, 1.0f);
    red[c] = g_gsum[g * 128 + c] / d * Wout[c];
    __syncthreads();
    for (int s = 64; s > 0; s >>= 1) {
        if (c < s) red[c] += red[c + s];
        __syncthreads();
    }
    if (c == 0) out[g] = red[0] + bout[0] + obias[0];
}

// ---------------- host ----------------
extern "C" void kernel_launch(void* const* d_in, const int* in_sizes, int n_in,
                              void* d_out, int out_size) {
    const float* x    = (const float*)d_in[0];
    const void*  ei   = d_in[1];
    const float* ea   = (const float*)d_in[2];
    const void*  ba   = d_in[3];
    const float* Wq   = (const float*)d_in[4];
    const float* bq   = (const float*)d_in[5];
    const float* Wk   = (const float*)d_in[6];
    const float* bk   = (const float*)d_in[7];
    const float* Wv   = (const float*)d_in[8];
    const float* bv   = (const float*)d_in[9];
    const float* We   = (const float*)d_in[10];
    const float* be   = (const float*)d_in[11];
    const float* Ws   = (const float*)d_in[12];
    const float* bs   = (const float*)d_in[13];
    const float* Wb   = (const float*)d_in[14];
    const float* gam  = (const float*)d_in[15];
    const float* bet  = (const float*)d_in[16];
    const float* Wout = (const float*)d_in[17];
    const float* bout = (const float*)d_in[18];
    const float* obia = (const float*)d_in[19];

    static int smem_set = 0;
    if (!smem_set) {
        cudaFuncSetAttribute(k_gemm_mma, cudaFuncAttributeMaxDynamicSharedMemorySize, SM_TOT);
        smem_set = 1;
    }

    k_detect<<<1, 32>>>(ei, ba);
    k_convert<<<(2 * Ee + 255) / 256, 256>>>(ei, ba);
    k_splitW<<<(12 * 2048 + 255) / 256, 256>>>(Wq, Wk, Wv, Ws);
    // layer-0 GEMM as launch #4 -> gets captured by the profiler
    k_gemm_mma<<<dim3(TILES, 4), 256, SM_TOT>>>(x, 0, bq, bk, bv, bs);
    // CSR build (once; edges fixed across layers)
    k_zerodeg<<<(Nn + 255) / 256, 256>>>();
    k_hist<<<(Ee + 255) / 256, 256>>>();
    k_scan<<<1, 1024>>>();
    k_copyoff<<<(Nn + 255) / 256, 256>>>();
    k_scatter<<<(Ee + 255) / 256, 256>>>(ea);

    for (int l = 0; l < Lr; l++) {
        if (l > 0)
            k_gemm_mma<<<dim3(TILES, 4), 256, SM_TOT>>>(nullptr, l, bq, bk, bv, bs);
        k_edge<<<(Nn * 32 + 255) / 256, 256>>>(We + l * 256, be + l * 128);
        k_zerobn<<<1, 128>>>();
        k_gate<<<(Nn + 7) / 8, 256>>>(Wb + l * 384);
        k_bnstats<<<1, 128>>>(gam + l * 128, bet + l * 128);
        k_bnelu<<<(Nn * 128 + 255) / 256, 256>>>();
    }

    k_poolinit<<<(Gg * 128 + 255) / 256, 256>>>();
    k_pool<<<(Nn * 32 + 255) / 256, 256>>>();
    k_read<<<Gg, 128>>>(Wout, bout, obia, (float*)d_out);
}

// round 9
// speedup vs baseline: 1.8181x; 1.0213x over previous
#include <cuda_runtime.h>
#include <cuda_bf16.h>
#include <math.h>
#include <stdint.h>

#define Nn 50000
#define Ee 800000
#define Gg 50
#define Lr 3
#define TILES 391            // ceil(50000/128)
#define PADK 136             // smem row stride in bf16 (272B, conflict-free for ldmatrix)

// ---------------- static device scratch (no runtime alloc allowed) ----------------
__device__ float g_qkvs[(size_t)Nn * 512];   // per layer: [q | - | - | x_r]
__device__ __nv_bfloat16 g_kv16[(size_t)Nn * 256];  // packed bf16 [k(128) | v(128)] per node
__device__ float g_outb[(size_t)Nn * 128];   // attention output / gated output (pre-BN)
__device__ float g_bnsum[128];
__device__ float g_bnsq[128];
__device__ float g_bnsc[128];
__device__ float g_bnsh[128];
__device__ int   g_esrc[Ee];
__device__ int   g_edst[Ee];
__device__ int   g_batch[Nn];
__device__ float g_gsum[Gg * 128];
__device__ float g_gcnt[Gg];
__device__ int   g_flags[2];
// CSR by destination
__device__ int   g_deg[Nn];
__device__ int   g_rowptr[Nn + 1];
__device__ int   g_workoff[Nn];
__device__ int   g_csrc[Ee];
__device__ float2 g_cea[Ee];
// W split+transpose staging: [l*4+mat][n][k] bf16 hi/lo, unswizzled
__device__ __nv_bfloat16 g_Whi[12 * 16384];
__device__ __nv_bfloat16 g_Wlo[12 * 16384];

// ---------------- helpers ----------------
__device__ __forceinline__ uint32_t smem_u32(const void* p) {
    uint32_t a;
    asm("{ .reg .u64 t; cvta.to.shared.u64 t, %1; cvt.u32.u64 %0, t; }" : "=r"(a) : "l"(p));
    return a;
}

// ---------------- dtype sniffing: int64 vs int32 index tensors ----------------
__global__ void k_detect(const void* ei, const void* ba) {
    if (threadIdx.x == 0 && blockIdx.x == 0) {
        const unsigned int* p = (const unsigned int*)ei;
        unsigned int acc = 0;
        long long half_e = (long long)Ee - 1;
        for (int j = 0; j < 64; j++) {
            long long i = half_e * j / 63;
            acc |= p[2 * i + 1];
        }
        g_flags[0] = (acc == 0) ? 1 : 0;
        const unsigned int* q = (const unsigned int*)ba;
        unsigned int acc2 = 0;
        long long half_n = (long long)Nn / 2 - 1;
        for (int j = 0; j < 64; j++) {
            long long i = half_n * j / 63;
            acc2 |= q[2 * i + 1];
        }
        g_flags[1] = (acc2 == 0) ? 1 : 0;
    }
}

__global__ void k_convert(const void* ei, const void* ba) {
    int i = blockIdx.x * blockDim.x + threadIdx.x;
    int f0 = g_flags[0], f1 = g_flags[1];
    if (i < 2 * Ee) {
        int v = f0 ? (int)((const long long*)ei)[i] : ((const int*)ei)[i];
        if (i < Ee) g_esrc[i] = v;
        else        g_edst[i - Ee] = v;
    }
    if (i < Nn) {
        g_batch[i] = f1 ? (int)((const long long*)ba)[i] : ((const int*)ba)[i];
    }
}

// ---------------- CSR build ----------------
__global__ void k_zerodeg() {
    int i = blockIdx.x * blockDim.x + threadIdx.x;
    if (i < Nn) g_deg[i] = 0;
}
__global__ void k_hist() {
    int i = blockIdx.x * blockDim.x + threadIdx.x;
    if (i < Ee) atomicAdd(&g_deg[g_edst[i]], 1);
}
__global__ void __launch_bounds__(1024) k_scan() {
    __shared__ int sm[1024];
    int tid = threadIdx.x;
    int run = 0;
    for (int base = 0; base < Nn; base += 1024) {
        int i = base + tid;
        int v = (i < Nn) ? g_deg[i] : 0;
        sm[tid] = v;
        __syncthreads();
        for (int off = 1; off < 1024; off <<= 1) {
            int t = (tid >= off) ? sm[tid - off] : 0;
            __syncthreads();
            sm[tid] += t;
            __syncthreads();
        }
        if (i < Nn) g_rowptr[i] = run + sm[tid] - v;   // exclusive
        run += sm[1023];
        __syncthreads();
    }
    if (tid == 0) g_rowptr[Nn] = run;
}
__global__ void k_copyoff() {
    int i = blockIdx.x * blockDim.x + threadIdx.x;
    if (i < Nn) g_workoff[i] = g_rowptr[i];
}
__global__ void k_scatter(const float* __restrict__ edge_attr) {
    int i = blockIdx.x * blockDim.x + threadIdx.x;
    if (i >= Ee) return;
    int dst = g_edst[i];
    int pos = atomicAdd(&g_workoff[dst], 1);
    g_csrc[pos] = g_esrc[i];
    g_cea[pos] = make_float2(edge_attr[i * 2 + 0], edge_attr[i * 2 + 1]);
}

// ---------------- W split + transpose (12 mats, once per launch) --------------
__global__ void k_splitW(const float* __restrict__ Wq, const float* __restrict__ Wk,
                         const float* __restrict__ Wv, const float* __restrict__ Ws) {
    int i = blockIdx.x * blockDim.x + threadIdx.x;   // over 12*2048 chunks of 8
    if (i >= 12 * 2048) return;
    int lm = i >> 11;
    int cidx = i & 2047;
    int j = cidx >> 4;          // output col / B row
    int kc = cidx & 15;         // k chunk of 8
    int l = lm >> 2, mat = lm & 3;
    const float* W = (mat == 0 ? Wq : mat == 1 ? Wk : mat == 2 ? Wv : Ws)
                   + (size_t)l * 16384;
    __nv_bfloat16 hi[8], lo[8];
    #pragma unroll
    for (int s = 0; s < 8; s++) {
        float v = W[(kc * 8 + s) * 128 + j];
        hi[s] = __float2bfloat16(v);
        lo[s] = __float2bfloat16(v - __bfloat162float(hi[s]));
    }
    size_t base = (size_t)lm * 16384 + j * 128 + kc * 8;
    *(uint4*)(g_Whi + base) = *(uint4*)hi;
    *(uint4*)(g_Wlo + base) = *(uint4*)lo;
}

// ---------------- warp-MMA GEMM: 128x128x128 tile, bf16 multi-pass fp32 --------
// passes: 0: Ahi*Whi, 1: Alo*Whi, 2: Ahi*Wlo. K/V (mat 1,2) use 2 passes only
// (their outputs are rounded to bf16 anyway). Q/skip use all 3.
// For l>0 (Asrc==nullptr) the A-load applies BN (bnsc/bnsh) + ELU to g_outb.
#define SM_AHI 0
#define SM_ALO (128 * PADK * 2)
#define SM_WHI (2 * 128 * PADK * 2)
#define SM_WLO (3 * 128 * PADK * 2)
#define SM_TOT (4 * 128 * PADK * 2)

__global__ void __launch_bounds__(256) k_gemm_mma(
    const float* __restrict__ Asrc,  // nullptr -> g_outb with BN+ELU applied
    int l, const float* __restrict__ bq, const float* __restrict__ bk,
    const float* __restrict__ bv, const float* __restrict__ bs)
{
    extern __shared__ __align__(16) char sm[];
    int tid = threadIdx.x;
    int t = blockIdx.x, mat = blockIdx.y;

    // ---- load & split A (optionally fused BN+ELU) ----
    {
        int r = tid >> 1, hf = tid & 1;
        int row = t * 128 + r;
        __nv_bfloat16* dhi = (__nv_bfloat16*)(sm + SM_AHI) + r * PADK + hf * 64;
        __nv_bfloat16* dlo = (__nv_bfloat16*)(sm + SM_ALO) + r * PADK + hf * 64;
        if (row < Nn) {
            const float* srcp = Asrc ? (Asrc + (size_t)row * 128 + hf * 64)
                                     : (g_outb + (size_t)row * 128 + hf * 64);
            #pragma unroll
            for (int c = 0; c < 8; c++) {
                float4 v0 = ((const float4*)srcp)[c * 2];
                float4 v1 = ((const float4*)srcp)[c * 2 + 1];
                float vs[8] = {v0.x, v0.y, v0.z, v0.w, v1.x, v1.y, v1.z, v1.w};
                if (!Asrc) {
                    int cb = hf * 64 + c * 8;
                    #pragma unroll
                    for (int s = 0; s < 8; s++) {
                        float y = vs[s] * g_bnsc[cb + s] + g_bnsh[cb + s];
                        vs[s] = y > 0.0f ? y : expm1f(y);
                    }
                }
                __nv_bfloat16 hi[8], lo[8];
                #pragma unroll
                for (int s = 0; s < 8; s++) {
                    hi[s] = __float2bfloat16(vs[s]);
                    lo[s] = __float2bfloat16(vs[s] - __bfloat162float(hi[s]));
                }
                *(uint4*)(dhi + c * 8) = *(uint4*)hi;
                *(uint4*)(dlo + c * 8) = *(uint4*)lo;
            }
        } else {
            uint4 z = make_uint4(0, 0, 0, 0);
            #pragma unroll
            for (int c = 0; c < 8; c++) {
                *(uint4*)(dhi + c * 8) = z;
                *(uint4*)(dlo + c * 8) = z;
            }
        }
    }
    // ---- load W hi/lo from staging ----
    {
        int n = tid >> 1, hf = tid & 1;
        size_t base = (size_t)(l * 4 + mat) * 16384 + n * 128 + hf * 64;
        const uint4* shi = (const uint4*)(g_Whi + base);
        const uint4* slo = (const uint4*)(g_Wlo + base);
        uint4* dhi = (uint4*)((__nv_bfloat16*)(sm + SM_WHI) + n * PADK + hf * 64);
        uint4* dlo = (uint4*)((__nv_bfloat16*)(sm + SM_WLO) + n * PADK + hf * 64);
        #pragma unroll
        for (int c = 0; c < 8; c++) { dhi[c] = shi[c]; dlo[c] = slo[c]; }
    }
    __syncthreads();

    int wid = tid >> 5, lane = tid & 31;
    int wr = wid >> 1, wc = wid & 1;
    int m0 = wr * 32, n0 = wc * 64;

    int quad = lane >> 3, qr = lane & 7;
    int a_row = ((quad & 1) << 3) + qr;
    int a_kof = (quad & 2) << 2;
    int b_row = qr;
    int b_kof = (quad & 1) << 3;

    uint32_t sb = smem_u32(sm);
    bool iskv = (mat == 1) || (mat == 2);
    int npass = iskv ? 2 : 3;

    float acc[2][8][4];
    #pragma unroll
    for (int mt = 0; mt < 2; mt++)
        #pragma unroll
        for (int nt = 0; nt < 8; nt++)
            #pragma unroll
            for (int c = 0; c < 4; c++) acc[mt][nt][c] = 0.0f;

    for (int pass = 0; pass < npass; pass++) {
        uint32_t ab = sb + (pass == 1 ? SM_ALO : SM_AHI);
        uint32_t wb = sb + (pass == 2 ? SM_WLO : SM_WHI);
        #pragma unroll
        for (int ks = 0; ks < 8; ks++) {
            int k0 = ks * 16;
            uint32_t af[2][4];
            #pragma unroll
            for (int mt = 0; mt < 2; mt++) {
                uint32_t addr = ab + ((m0 + mt * 16 + a_row) * PADK + k0 + a_kof) * 2;
                asm volatile("ldmatrix.sync.aligned.m8n8.x4.shared.b16 {%0,%1,%2,%3}, [%4];"
                             : "=r"(af[mt][0]), "=r"(af[mt][1]), "=r"(af[mt][2]), "=r"(af[mt][3])
                             : "r"(addr));
            }
            #pragma unroll
            for (int nt = 0; nt < 8; nt++) {
                uint32_t bf[2];
                uint32_t addr = wb + ((n0 + nt * 8 + b_row) * PADK + k0 + b_kof) * 2;
                asm volatile("ldmatrix.sync.aligned.m8n8.x2.shared.b16 {%0,%1}, [%2];"
                             : "=r"(bf[0]), "=r"(bf[1]) : "r"(addr));
                #pragma unroll
                for (int mt = 0; mt < 2; mt++) {
                    asm volatile(
                        "mma.sync.aligned.m16n8k16.row.col.f32.bf16.bf16.f32 "
                        "{%0,%1,%2,%3}, {%4,%5,%6,%7}, {%8,%9}, {%0,%1,%2,%3};"
                        : "+f"(acc[mt][nt][0]), "+f"(acc[mt][nt][1]),
                          "+f"(acc[mt][nt][2]), "+f"(acc[mt][nt][3])
                        : "r"(af[mt][0]), "r"(af[mt][1]), "r"(af[mt][2]), "r"(af[mt][3]),
                          "r"(bf[0]), "r"(bf[1]));
                }
            }
        }
    }

    // ---- epilogue: q/skip -> fp32 g_qkvs; k/v -> packed bf16 g_kv16 ----
    const float* bias = (mat == 0 ? bq : mat == 1 ? bk : mat == 2 ? bv : bs) + l * 128;
    int drow = lane >> 2, dcol = (lane & 3) * 2;
    int kvoff = (mat == 1) ? 0 : 128;
    #pragma unroll
    for (int mt = 0; mt < 2; mt++) {
        #pragma unroll
        for (int nt = 0; nt < 8; nt++) {
            int col = n0 + nt * 8 + dcol;
            float b0 = bias[col], b1 = bias[col + 1];
            int r0 = t * 128 + m0 + mt * 16 + drow;
            if (r0 < Nn) {
                float v0 = acc[mt][nt][0] + b0, v1 = acc[mt][nt][1] + b1;
                if (iskv) {
                    __nv_bfloat162 p = {__float2bfloat16(v0), __float2bfloat16(v1)};
                    *(__nv_bfloat162*)(g_kv16 + (size_t)r0 * 256 + kvoff + col) = p;
                } else {
                    *(float2*)(g_qkvs + (size_t)r0 * 512 + mat * 128 + col) =
                        make_float2(v0, v1);
                }
            }
            int r1 = r0 + 8;
            if (r1 < Nn) {
                float v0 = acc[mt][nt][2] + b0, v1 = acc[mt][nt][3] + b1;
                if (iskv) {
                    __nv_bfloat162 p = {__float2bfloat16(v0), __float2bfloat16(v1)};
                    *(__nv_bfloat162*)(g_kv16 + (size_t)r1 * 256 + kvoff + col) = p;
                } else {
                    *(float2*)(g_qkvs + (size_t)r1 * 512 + mat * 128 + col) =
                        make_float2(v0, v1);
                }
            }
        }
    }
}

// ---------------- fused edge phase: warp per destination node, ONE loop --------
//   logit = scale*q.k + a0*t0 + a1*t1 + tb    (t* = per-head scale*q.We dots)
//   accumulate msg += ex*v unnormalized; normalize + add edge-emb terms at end.
__global__ void __launch_bounds__(256) k_edge(const float* __restrict__ We,
                                              const float* __restrict__ be)
{
    int n = (blockIdx.x * blockDim.x + threadIdx.x) >> 5;
    int lane = threadIdx.x & 31;
    if (n >= Nn) return;
    int s = g_rowptr[n], eend = g_rowptr[n + 1];

    float4 qv = ((const float4*)(g_qkvs + (size_t)n * 512))[lane];
    float4 w0 = ((const float4*)We)[lane];
    float4 w1 = ((const float4*)(We + 128))[lane];
    float4 bb = ((const float4*)be)[lane];
    const float scale = 0.17677669529663687f;   // 1/sqrt(32)

    // per-head projections of q onto We rows and be (broadcast within head)
    float p0 = qv.x * w0.x + qv.y * w0.y + qv.z * w0.z + qv.w * w0.w;
    float p1 = qv.x * w1.x + qv.y * w1.y + qv.z * w1.z + qv.w * w1.w;
    float pb = qv.x * bb.x + qv.y * bb.y + qv.z * bb.z + qv.w * bb.w;
    #pragma unroll
    for (int m = 4; m > 0; m >>= 1) {
        p0 += __shfl_xor_sync(0xffffffffu, p0, m);
        p1 += __shfl_xor_sync(0xffffffffu, p1, m);
        pb += __shfl_xor_sync(0xffffffffu, pb, m);
    }
    float t0 = p0 * scale, t1 = p1 * scale, tb = pb * scale;

    float den = 0.0f, S0 = 0.0f, S1 = 0.0f;
    float4 msg = make_float4(0.f, 0.f, 0.f, 0.f);
    for (int e = s; e < eend; e++) {
        int src = g_csrc[e];
        float2 a = g_cea[e];
        const __nv_bfloat16* kvrow = g_kv16 + (size_t)src * 256;
        uint2 kr = *(const uint2*)(kvrow + lane * 4);
        uint2 vr = *(const uint2*)(kvrow + 128 + lane * 4);
        float2 k0 = __bfloat1622float2(*(__nv_bfloat162*)&kr.x);
        float2 k1 = __bfloat1622float2(*(__nv_bfloat162*)&kr.y);
        float d = qv.x * k0.x + qv.y * k0.y + qv.z * k1.x + qv.w * k1.y;
        d += __shfl_xor_sync(0xffffffffu, d, 4);
        d += __shfl_xor_sync(0xffffffffu, d, 2);
        d += __shfl_xor_sync(0xffffffffu, d, 1);
        float logit = fmaf(d, scale, fmaf(a.x, t0, fmaf(a.y, t1, tb)));
        float ex = expf(logit);
        den += ex;
        S0 = fmaf(ex, a.x, S0);
        S1 = fmaf(ex, a.y, S1);
        float2 v0 = __bfloat1622float2(*(__nv_bfloat162*)&vr.x);
        float2 v1 = __bfloat1622float2(*(__nv_bfloat162*)&vr.y);
        msg.x = fmaf(ex, v0.x, msg.x);
        msg.y = fmaf(ex, v0.y, msg.y);
        msg.z = fmaf(ex, v1.x, msg.z);
        msg.w = fmaf(ex, v1.y, msg.w);
    }
    float inv = 1.0f / (den + 1e-16f);
    float c0 = S0 * inv, c1 = S1 * inv, cb = den * inv;

    float4 o;
    o.x = fmaf(msg.x, inv, fmaf(c0, w0.x, fmaf(c1, w1.x, cb * bb.x)));
    o.y = fmaf(msg.y, inv, fmaf(c0, w0.y, fmaf(c1, w1.y, cb * bb.y)));
    o.z = fmaf(msg.z, inv, fmaf(c0, w0.z, fmaf(c1, w1.z, cb * bb.z)));
    o.w = fmaf(msg.w, inv, fmaf(c0, w0.w, fmaf(c1, w1.w, cb * bb.w)));
    ((float4*)(g_outb + (size_t)n * 128))[lane] = o;
}

// ---------------- BN accumulator zero (per layer) ----------------
__global__ void k_zerobn() {
    int c = threadIdx.x;
    if (c < 128) { g_bnsum[c] = 0.0f; g_bnsq[c] = 0.0f; }
}

// ---------------- beta gate + BN partial stats (warp per node, 8 nodes/block) ----
__global__ void k_gate(const float* __restrict__ Wbeta) {
    __shared__ float ssum[128];
    __shared__ float ssq[128];
    int tid = threadIdx.x;
    if (tid < 128) { ssum[tid] = 0.0f; ssq[tid] = 0.0f; }
    __syncthreads();
    int lane = tid & 31;
    int n = blockIdx.x * 8 + (tid >> 5);
    if (n < Nn) {
        float4 o = ((const float4*)(g_outb + (size_t)n * 128))[lane];
        float4 xr = ((const float4*)(g_qkvs + (size_t)n * 512 + 384))[lane];
        float4 w1 = ((const float4*)Wbeta)[lane];
        float4 w2 = ((const float4*)(Wbeta + 128))[lane];
        float4 w3 = ((const float4*)(Wbeta + 256))[lane];
        float s = o.x * w1.x + o.y * w1.y + o.z * w1.z + o.w * w1.w
                + xr.x * w2.x + xr.y * w2.y + xr.z * w2.z + xr.w * w2.w
                + (o.x - xr.x) * w3.x + (o.y - xr.y) * w3.y
                + (o.z - xr.z) * w3.z + (o.w - xr.w) * w3.w;
        #pragma unroll
        for (int m = 16; m > 0; m >>= 1) s += __shfl_xor_sync(0xffffffffu, s, m);
        float g = 1.0f / (1.0f + expf(-s));
        float4 no;
        no.x = g * xr.x + (1.0f - g) * o.x;
        no.y = g * xr.y + (1.0f - g) * o.y;
        no.z = g * xr.z + (1.0f - g) * o.z;
        no.w = g * xr.w + (1.0f - g) * o.w;
        ((float4*)(g_outb + (size_t)n * 128))[lane] = no;
        int c = lane * 4;
        atomicAdd(&ssum[c + 0], no.x); atomicAdd(&ssq[c + 0], no.x * no.x);
        atomicAdd(&ssum[c + 1], no.y); atomicAdd(&ssq[c + 1], no.y * no.y);
        atomicAdd(&ssum[c + 2], no.z); atomicAdd(&ssq[c + 2], no.z * no.z);
        atomicAdd(&ssum[c + 3], no.w); atomicAdd(&ssq[c + 3], no.w * no.w);
    }
    __syncthreads();
    if (tid < 128) {
        atomicAdd(&g_bnsum[tid], ssum[tid]);
        atomicAdd(&g_bnsq[tid], ssq[tid]);
    }
}

// ---------------- BN finalize ----------------
__global__ void k_bnstats(const float* __restrict__ gamma, const float* __restrict__ beta) {
    int c = threadIdx.x;
    if (c < 128) {
        float mu = g_bnsum[c] / (float)Nn;
        float var = g_bnsq[c] / (float)Nn - mu * mu;
        float rs = rsqrtf(var + 1e-5f);
        float sc = gamma[c] * rs;
        g_bnsc[c] = sc;
        g_bnsh[c] = beta[c] - mu * sc;
    }
}

// ---------------- readout (applies final-layer BN + ELU on the fly) ------------
__global__ void k_poolinit() {
    int i = blockIdx.x * blockDim.x + threadIdx.x;
    if (i < Gg * 128) g_gsum[i] = 0.0f;
    if (i < Gg) g_gcnt[i] = 0.0f;
}

__global__ void k_pool() {
    int wid = (blockIdx.x * blockDim.x + threadIdx.x) >> 5;
    int lane = threadIdx.x & 31;
    if (wid >= Nn) return;
    int b = g_batch[wid];
    float4 v = ((const float4*)(g_outb + (size_t)wid * 128))[lane];
    int c = lane * 4;
    float4 sc = *(const float4*)(g_bnsc + c);
    float4 sh = *(const float4*)(g_bnsh + c);
    v.x = v.x * sc.x + sh.x; v.x = v.x > 0.f ? v.x : expm1f(v.x);
    v.y = v.y * sc.y + sh.y; v.y = v.y > 0.f ? v.y : expm1f(v.y);
    v.z = v.z * sc.z + sh.z; v.z = v.z > 0.f ? v.z : expm1f(v.z);
    v.w = v.w * sc.w + sh.w; v.w = v.w > 0.f ? v.w : expm1f(v.w);
    float* o = g_gsum + b * 128 + c;
    atomicAdd(o + 0, v.x);
    atomicAdd(o + 1, v.y);
    atomicAdd(o + 2, v.z);
    atomicAdd(o + 3, v.w);
    if (lane == 0) atomicAdd(&g_gcnt[b], 1.0f);
}

__global__ void k_read(const float* __restrict__ Wout, const float* __restrict__ bout,
                       const float* __restrict__ obias, float* __restrict__ out) {
    __shared__ float red[128];
    int g = blockIdx.x;
    int c = threadIdx.x;
    float cnt = g_gcnt[g];
    float d = fmaxf(cnt, 1.0f);
    red[c] = g_gsum[g * 128 + c] / d * Wout[c];
    __syncthreads();
    for (int s = 64; s > 0; s >>= 1) {
        if (c < s) red[c] += red[c + s];
        __syncthreads();
    }
    if (c == 0) out[g] = red[0] + bout[0] + obias[0];
}

// ---------------- host ----------------
extern "C" void kernel_launch(void* const* d_in, const int* in_sizes, int n_in,
                              void* d_out, int out_size) {
    const float* x    = (const float*)d_in[0];
    const void*  ei   = d_in[1];
    const float* ea   = (const float*)d_in[2];
    const void*  ba   = d_in[3];
    const float* Wq   = (const float*)d_in[4];
    const float* bq   = (const float*)d_in[5];
    const float* Wk   = (const float*)d_in[6];
    const float* bk   = (const float*)d_in[7];
    const float* Wv   = (const float*)d_in[8];
    const float* bv   = (const float*)d_in[9];
    const float* We   = (const float*)d_in[10];
    const float* be   = (const float*)d_in[11];
    const float* Ws   = (const float*)d_in[12];
    const float* bs   = (const float*)d_in[13];
    const float* Wb   = (const float*)d_in[14];
    const float* gam  = (const float*)d_in[15];
    const float* bet  = (const float*)d_in[16];
    const float* Wout = (const float*)d_in[17];
    const float* bout = (const float*)d_in[18];
    const float* obia = (const float*)d_in[19];

    static int smem_set = 0;
    if (!smem_set) {
        cudaFuncSetAttribute(k_gemm_mma, cudaFuncAttributeMaxDynamicSharedMemorySize, SM_TOT);
        smem_set = 1;
    }

    k_detect<<<1, 32>>>(ei, ba);
    k_convert<<<(2 * Ee + 255) / 256, 256>>>(ei, ba);
    k_splitW<<<(12 * 2048 + 255) / 256, 256>>>(Wq, Wk, Wv, Ws);
    // layer-0 GEMM as launch #4 -> gets captured by the profiler
    k_gemm_mma<<<dim3(TILES, 4), 256, SM_TOT>>>(x, 0, bq, bk, bv, bs);
    // CSR build (once; edges fixed across layers)
    k_zerodeg<<<(Nn + 255) / 256, 256>>>();
    k_hist<<<(Ee + 255) / 256, 256>>>();
    k_scan<<<1, 1024>>>();
    k_copyoff<<<(Nn + 255) / 256, 256>>>();
    k_scatter<<<(Ee + 255) / 256, 256>>>(ea);

    for (int l = 0; l < Lr; l++) {
        if (l > 0)
            k_gemm_mma<<<dim3(TILES, 4), 256, SM_TOT>>>(nullptr, l, bq, bk, bv, bs);
        k_edge<<<(Nn * 32 + 255) / 256, 256>>>(We + l * 256, be + l * 128);
        k_zerobn<<<1, 128>>>();
        k_gate<<<(Nn + 7) / 8, 256>>>(Wb + l * 384);
        k_bnstats<<<1, 128>>>(gam + l * 128, bet + l * 128);
    }

    k_poolinit<<<(Gg * 128 + 255) / 256, 256>>>();
    k_pool<<<(Nn * 32 + 255) / 256, 256>>>();
    k_read<<<Gg, 128>>>(Wout, bout, obia, (float*)d_out);
}